// round 6
// baseline (speedup 1.0000x reference)
#include <cuda_runtime.h>
#include <cuda_bf16.h>
#include <math.h>
#include <stdint.h>

// Problem constants
#define BB 2
#define TT 2048
#define HIDD 2048
#define NH 16
#define NKV 8
#define HD 128
#define QKVW 4096   // (NH + 2*NKV) * HD
#define KOFF 2048   // NH*HD
#define VOFF 3072   // NH*HD + NKV*HD
#define ATT_SCALE 0.08838834764831845f  // 128^-0.5

// Scratch (allocation-free rule: __device__ globals)
__device__ float g_qkv[(size_t)BB * TT * QKVW];                 // 64 MB fp32
__device__ __nv_bfloat16 g_hid_hi[(size_t)BB * TT * HIDD];
__device__ __nv_bfloat16 g_hid_lo[(size_t)BB * TT * HIDD];
__device__ __nv_bfloat16 g_wqkv_hi[(size_t)QKVW * HIDD];
__device__ __nv_bfloat16 g_wqkv_lo[(size_t)QKVW * HIDD];
__device__ __nv_bfloat16 g_wo_hi[(size_t)HIDD * HIDD];
__device__ __nv_bfloat16 g_wo_lo[(size_t)HIDD * HIDD];
__device__ __nv_bfloat16 g_qkvb_hi[(size_t)BB * TT * QKVW];
__device__ __nv_bfloat16 g_qkvb_lo[(size_t)BB * TT * QKVW];
__device__ __nv_bfloat16 g_attnb_hi[(size_t)BB * TT * HIDD];
__device__ __nv_bfloat16 g_attnb_lo[(size_t)BB * TT * HIDD];

// ---------------------------------------------------------------------------
// Helpers (arch-stable PTX: cp.async + ldmatrix + mma.sync, sm_80 level)
// ---------------------------------------------------------------------------
__device__ __forceinline__ uint32_t smem_u32(const void* p) {
    uint32_t a;
    asm("{ .reg .u64 t; cvta.to.shared.u64 t, %1; cvt.u32.u64 %0, t; }"
        : "=r"(a) : "l"(p));
    return a;
}

// pack two f32 -> bf16x2 (lo half = x, hi half = y), round-to-nearest
__device__ __forceinline__ uint32_t pack_bf2(float x, float y) {
    uint32_t r;
    asm("cvt.rn.bf16x2.f32 %0, %1, %2;" : "=r"(r) : "f"(y), "f"(x));
    return r;
}

#define LDM_X4(r, a)                                                            \
    asm volatile("ldmatrix.sync.aligned.m8n8.x4.shared.b16 {%0,%1,%2,%3}, [%4];"\
        : "=r"((r)[0]), "=r"((r)[1]), "=r"((r)[2]), "=r"((r)[3]) : "r"(a))

#define LDM_X4T(r, a)                                                           \
    asm volatile("ldmatrix.sync.aligned.m8n8.x4.trans.shared.b16 "              \
                 "{%0,%1,%2,%3}, [%4];"                                         \
        : "=r"((r)[0]), "=r"((r)[1]), "=r"((r)[2]), "=r"((r)[3]) : "r"(a))

__device__ __forceinline__ void mma_bf16(float* d, const uint32_t* a, const uint32_t* b) {
    asm volatile(
        "mma.sync.aligned.m16n8k16.row.col.f32.bf16.bf16.f32 "
        "{%0,%1,%2,%3}, {%4,%5,%6,%7}, {%8,%9}, {%0,%1,%2,%3};"
        : "+f"(d[0]), "+f"(d[1]), "+f"(d[2]), "+f"(d[3])
        : "r"(a[0]), "r"(a[1]), "r"(a[2]), "r"(a[3]), "r"(b[0]), "r"(b[1]));
}

#define CP_A16(dst, src)                                                        \
    asm volatile("cp.async.cg.shared.global [%0], [%1], 16;"                    \
        :: "r"(dst), "l"(src))
#define CP_COMMIT() asm volatile("cp.async.commit_group;" ::: "memory")
#define CP_WAIT(n)  asm volatile("cp.async.wait_group %0;" :: "n"(n) : "memory")

// ---------------------------------------------------------------------------
// split: fp32 -> bf16 hi + bf16 lo (x = hi + lo)
// ---------------------------------------------------------------------------
__global__ void split_kernel(const float* __restrict__ src,
                             __nv_bfloat16* __restrict__ hi,
                             __nv_bfloat16* __restrict__ lo, int n4)
{
    int i = blockIdx.x * blockDim.x + threadIdx.x;
    if (i >= n4) return;
    float4 v = ((const float4*)src)[i];
    uint32_t h0 = pack_bf2(v.x, v.y), h1 = pack_bf2(v.z, v.w);
    float lx = v.x - __uint_as_float(h0 << 16);
    float ly = v.y - __uint_as_float(h0 & 0xFFFF0000u);
    float lz = v.z - __uint_as_float(h1 << 16);
    float lw = v.w - __uint_as_float(h1 & 0xFFFF0000u);
    ((uint2*)hi)[i] = make_uint2(h0, h1);
    ((uint2*)lo)[i] = make_uint2(pack_bf2(lx, ly), pack_bf2(lz, lw));
}

// ---------------------------------------------------------------------------
// RoPE (Q,K) + bf16 split of the whole QKV row; Q additionally pre-scaled
// by ATT_SCALE (folded out of the attention score computation).
// ---------------------------------------------------------------------------
__global__ void ropesplit_kernel(const float* __restrict__ cosT,
                                 const float* __restrict__ sinT)
{
    const int bt   = blockIdx.x;
    const int t    = bt & (TT - 1);
    const int slot = blockIdx.y * blockDim.x + threadIdx.x;   // 0..1023
    const int col  = slot * 4;
    const float* row = g_qkv + (size_t)bt * QKVW;
    float4 v = *(const float4*)(row + col);

    if (col < VOFF) {   // Q or K head: rope
        int d  = col & (HD - 1);
        int dd = d & 63;
        float4 c = *(const float4*)(cosT + t * 64 + dd);
        float4 s = *(const float4*)(sinT + t * 64 + dd);
        if (d < 64) {
            float4 x2 = *(const float4*)(row + col + 64);
            v.x = v.x * c.x - x2.x * s.x;
            v.y = v.y * c.y - x2.y * s.y;
            v.z = v.z * c.z - x2.z * s.z;
            v.w = v.w * c.w - x2.w * s.w;
        } else {
            float4 x1 = *(const float4*)(row + col - 64);
            v.x = x1.x * s.x + v.x * c.x;
            v.y = x1.y * s.y + v.y * c.y;
            v.z = x1.z * s.z + v.z * c.z;
            v.w = x1.w * s.w + v.w * c.w;
        }
        if (col < KOFF) {   // Q: fold attention scale
            v.x *= ATT_SCALE; v.y *= ATT_SCALE; v.z *= ATT_SCALE; v.w *= ATT_SCALE;
        }
    }

    uint32_t h0 = pack_bf2(v.x, v.y), h1 = pack_bf2(v.z, v.w);
    float lx = v.x - __uint_as_float(h0 << 16);
    float ly = v.y - __uint_as_float(h0 & 0xFFFF0000u);
    float lz = v.z - __uint_as_float(h1 << 16);
    float lw = v.w - __uint_as_float(h1 & 0xFFFF0000u);
    size_t o = (size_t)bt * (QKVW / 4) + slot;
    ((uint2*)g_qkvb_hi)[o] = make_uint2(h0, h1);
    ((uint2*)g_qkvb_lo)[o] = make_uint2(pack_bf2(lx, ly), pack_bf2(lz, lw));
}

// ---------------------------------------------------------------------------
// Tensor-core NT GEMM on pre-split bf16 hi/lo inputs.
// C[M,N] = (Ah+Al)[M,K] @ (Bh+Bl)[N,K]^T, fp32 accumulate, 3 MMA products.
// CTA 128x128, BK=32, 8 warps (4m x 2n -> 32x64 warp tile).
// 2-stage cp.async pipeline, sized for 2 CTAs/SM (<=128 regs, 80 KB smem).
// SMEM rows: 32 bf16 + 8 pad = 80 B (conflict-free ldmatrix).
// ---------------------------------------------------------------------------
#define GT_BUF  10240                // one 128x32 bf16 tile (rows of 80 B)
#define GT_STG  (4 * GT_BUF)         // Ah, Al, Bh, Bl = 40960
#define GT_SMEM (2 * GT_STG)         // 2 stages = 81920

#define GT_ISSUE(c)                                                            \
    do {                                                                       \
        uint32_t sb_ = smb + ((c) & 1) * GT_STG;                               \
        _Pragma("unroll")                                                      \
        for (int i_ = 0; i_ < 8; i_++) {   /* 4 bufs x 512 chunks / 256 thr */ \
            const int bu_ = i_ >> 1;                                           \
            int w_ = (i_ & 1) * 256 + tid;                                     \
            int r_ = w_ >> 2, ch_ = w_ & 3;                                    \
            CP_A16(sb_ + bu_ * GT_BUF + r_ * 80 + ch_ * 16,                    \
                   tb[bu_] + (size_t)r_ * K + (c) * 32 + ch_ * 8);             \
        }                                                                      \
    } while (0)

__global__ void __launch_bounds__(256, 2) gemm_pre_kernel(
    const __nv_bfloat16* __restrict__ Ah, const __nv_bfloat16* __restrict__ Al,
    const __nv_bfloat16* __restrict__ Bh, const __nv_bfloat16* __restrict__ Bl,
    float* __restrict__ C, int M, int N, int K)
{
    extern __shared__ char sm[];
    const uint32_t smb = smem_u32(sm);
    const int tid = threadIdx.x;
    const int wid = tid >> 5, lane = tid & 31;
    const int m0 = blockIdx.y * 128, n0 = blockIdx.x * 128;
    const int wm = wid & 3, wn = wid >> 2;          // 4m x 2n, 32x64 each
    const int quad = lane >> 3, rin = lane & 7;

    const __nv_bfloat16* tb[4] = {
        Ah + (size_t)m0 * K, Al + (size_t)m0 * K,
        Bh + (size_t)n0 * K, Bl + (size_t)n0 * K };
    const int NC = K / 32;

    float acc[2][8][4];
#pragma unroll
    for (int i = 0; i < 2; i++)
#pragma unroll
        for (int j = 0; j < 8; j++)
#pragma unroll
            for (int u = 0; u < 4; u++) acc[i][j][u] = 0.f;

    GT_ISSUE(0); CP_COMMIT();
    GT_ISSUE(1); CP_COMMIT();

    for (int c = 0; c < NC; c++) {
        CP_WAIT(1);
        __syncthreads();

        const uint32_t aBase = smb + (c & 1) * GT_STG;
        const uint32_t bBase = aBase + 2 * GT_BUF;
#pragma unroll
        for (int ks = 0; ks < 2; ks++) {
            const int k0 = ks * 16;
            uint32_t afh[2][4], afl[2][4];
#pragma unroll
            for (int mt = 0; mt < 2; mt++) {
                int row = wm * 32 + mt * 16 + (quad & 1) * 8 + rin;
                int col = k0 + (quad >> 1) * 8;
                uint32_t ad = aBase + row * 80 + col * 2;
                LDM_X4(afh[mt], ad);
                LDM_X4(afl[mt], ad + GT_BUF);
            }
#pragma unroll
            for (int nb = 0; nb < 4; nb++) {
                uint32_t bh4[4], bl4[4];
                int rowb = wn * 64 + nb * 16 + (quad >> 1) * 8 + rin;
                int colb = k0 + (quad & 1) * 8;
                uint32_t bd = bBase + rowb * 80 + colb * 2;
                LDM_X4(bh4, bd);
                LDM_X4(bl4, bd + GT_BUF);
#pragma unroll
                for (int mt = 0; mt < 2; mt++)
#pragma unroll
                    for (int hf = 0; hf < 2; hf++) {
                        mma_bf16(acc[mt][nb * 2 + hf], afh[mt], &bh4[hf * 2]);
                        mma_bf16(acc[mt][nb * 2 + hf], afh[mt], &bl4[hf * 2]);
                        mma_bf16(acc[mt][nb * 2 + hf], afl[mt], &bh4[hf * 2]);
                    }
            }
        }

        __syncthreads();                 // stage (c&1) fully consumed
        if (c + 2 < NC) GT_ISSUE(c + 2);
        CP_COMMIT();
    }

    const int lr = lane >> 2;
    const int lc = (lane & 3) * 2;
#pragma unroll
    for (int mt = 0; mt < 2; mt++)
#pragma unroll
        for (int nt = 0; nt < 8; nt++) {
            int row = m0 + wm * 32 + mt * 16 + lr;
            int col = n0 + wn * 64 + nt * 8 + lc;
            *(float2*)(C + (size_t)row * N + col) =
                make_float2(acc[mt][nt][0], acc[mt][nt][1]);
            *(float2*)(C + (size_t)(row + 8) * N + col) =
                make_float2(acc[mt][nt][2], acc[mt][nt][3]);
        }
}

// ---------------------------------------------------------------------------
// Tensor-core causal GQA flash attention (bf16 split, fp32 accum).
// CTA: 64 Q rows x (head, batch); 4 warps, each warp owns 16 Q rows.
// ---------------------------------------------------------------------------
#define AQLD  272
#define ATILE 17408                 // 64 rows x 272 B
#define A_KH  (2 * ATILE)
#define A_VH  (4 * ATILE)
#define ATT_SMEM (6 * ATILE)        // 104448 B

__global__ void __launch_bounds__(128, 2) attn_kernel()
{
    extern __shared__ char sm[];
    const uint32_t smb = smem_u32(sm);
    const int tid = threadIdx.x;
    const int wid = tid >> 5, lane = tid & 31;
    const int q0 = blockIdx.x * 64;
    const int h = blockIdx.y, b = blockIdx.z;
    const int khh = h >> 1;                 // GQA: n_rep = 2

    const int l8  = (lane >> 3) & 1;
    const int l16 = lane >> 4;
    const int rin = lane & 7;

    // ---- load Q tile hi/lo once (cp.async) ----
    {
        const __nv_bfloat16* qh = g_qkvb_hi + ((size_t)(b * TT + q0)) * QKVW + h * HD;
        const __nv_bfloat16* ql = g_qkvb_lo + ((size_t)(b * TT + q0)) * QKVW + h * HD;
#pragma unroll
        for (int i = 0; i < 16; i++) {
            const int bufl = i >> 3;
            int w = (i & 7) * 128 + tid;
            int r = w >> 4, ch = w & 15;
            const __nv_bfloat16* src = (bufl ? ql : qh) + (size_t)r * QKVW + ch * 8;
            uint32_t dst = smb + bufl * ATILE + r * AQLD + ch * 16;
            CP_A16(dst, src);
        }
        CP_COMMIT();
    }

    float o[16][4];
#pragma unroll
    for (int i = 0; i < 16; i++)
#pragma unroll
        for (int u = 0; u < 4; u++) o[i][u] = 0.f;
    float m0r = -1e30f, m1r = -1e30f, l0 = 0.f, l1 = 0.f;

    const size_t bbase = (size_t)(b * TT);
    const int ntiles = (q0 >> 6) + 1;

    for (int jt = 0; jt < ntiles; jt++) {
        const int kb = jt << 6;
        __syncthreads();   // everyone done reading previous K/V tiles

        // ---- load K,V hi/lo tiles ----
        {
            const size_t rb = (bbase + kb) * QKVW;
            const __nv_bfloat16* s0 = g_qkvb_hi + rb + KOFF + khh * HD;
            const __nv_bfloat16* s1 = g_qkvb_lo + rb + KOFF + khh * HD;
            const __nv_bfloat16* s2 = g_qkvb_hi + rb + VOFF + khh * HD;
            const __nv_bfloat16* s3 = g_qkvb_lo + rb + VOFF + khh * HD;
#pragma unroll
            for (int i = 0; i < 32; i++) {
                const int t = i >> 3;
                int w = (i & 7) * 128 + tid;
                int r = w >> 4, ch = w & 15;
                const __nv_bfloat16* src =
                    (t == 0 ? s0 : t == 1 ? s1 : t == 2 ? s2 : s3)
                    + (size_t)r * QKVW + ch * 8;
                uint32_t dst = smb + A_KH + t * ATILE + r * AQLD + ch * 16;
                CP_A16(dst, src);
            }
            CP_COMMIT();
        }
        CP_WAIT(0);
        __syncthreads();

        // ---- S = Q @ K^T  (Q pre-scaled by ATT_SCALE) ----
        float s[8][4];
#pragma unroll
        for (int i = 0; i < 8; i++)
#pragma unroll
            for (int u = 0; u < 4; u++) s[i][u] = 0.f;

#pragma unroll
        for (int ks = 0; ks < 8; ks++) {
            const int k0 = ks * 16;
            uint32_t aqh[4], aql[4];
            uint32_t aaddr = smb + (wid * 16 + l8 * 8 + rin) * AQLD + (k0 + l16 * 8) * 2;
            LDM_X4(aqh, aaddr);
            LDM_X4(aql, aaddr + ATILE);
#pragma unroll
            for (int nb = 0; nb < 4; nb++) {
                uint32_t bh4[4], bl4[4];
                uint32_t baddr = smb + A_KH + (nb * 16 + l16 * 8 + rin) * AQLD
                               + (k0 + l8 * 8) * 2;
                LDM_X4(bh4, baddr);
                LDM_X4(bl4, baddr + ATILE);
#pragma unroll
                for (int hf = 0; hf < 2; hf++) {
                    mma_bf16(s[nb * 2 + hf], aqh, &bh4[hf * 2]);
                    mma_bf16(s[nb * 2 + hf], aqh, &bl4[hf * 2]);
                    mma_bf16(s[nb * 2 + hf], aql, &bh4[hf * 2]);
                }
            }
        }

        // ---- causal mask on the diagonal tile ----
        if (kb == q0) {
            const int r0l = wid * 16 + (lane >> 2);
#pragma unroll
            for (int nt = 0; nt < 8; nt++) {
                int c0 = nt * 8 + 2 * (lane & 3);
                if (c0     > r0l)     s[nt][0] = -1e30f;
                if (c0 + 1 > r0l)     s[nt][1] = -1e30f;
                if (c0     > r0l + 8) s[nt][2] = -1e30f;
                if (c0 + 1 > r0l + 8) s[nt][3] = -1e30f;
            }
        }

        // ---- register online softmax (rows lr and lr+8) ----
        float tm0 = -1e30f, tm1 = -1e30f;
#pragma unroll
        for (int nt = 0; nt < 8; nt++) {
            tm0 = fmaxf(tm0, fmaxf(s[nt][0], s[nt][1]));
            tm1 = fmaxf(tm1, fmaxf(s[nt][2], s[nt][3]));
        }
        tm0 = fmaxf(tm0, __shfl_xor_sync(0xffffffffu, tm0, 1));
        tm0 = fmaxf(tm0, __shfl_xor_sync(0xffffffffu, tm0, 2));
        tm1 = fmaxf(tm1, __shfl_xor_sync(0xffffffffu, tm1, 1));
        tm1 = fmaxf(tm1, __shfl_xor_sync(0xffffffffu, tm1, 2));
        float nm0 = fmaxf(m0r, tm0), nm1 = fmaxf(m1r, tm1);
        float cor0 = __expf(m0r - nm0), cor1 = __expf(m1r - nm1);
        m0r = nm0; m1r = nm1;

        float sum0 = 0.f, sum1 = 0.f;
#pragma unroll
        for (int nt = 0; nt < 8; nt++) {
            s[nt][0] = __expf(s[nt][0] - nm0);
            s[nt][1] = __expf(s[nt][1] - nm0);
            s[nt][2] = __expf(s[nt][2] - nm1);
            s[nt][3] = __expf(s[nt][3] - nm1);
            sum0 += s[nt][0] + s[nt][1];
            sum1 += s[nt][2] + s[nt][3];
        }
        sum0 += __shfl_xor_sync(0xffffffffu, sum0, 1);
        sum0 += __shfl_xor_sync(0xffffffffu, sum0, 2);
        sum1 += __shfl_xor_sync(0xffffffffu, sum1, 1);
        sum1 += __shfl_xor_sync(0xffffffffu, sum1, 2);
        l0 = l0 * cor0 + sum0;
        l1 = l1 * cor1 + sum1;

#pragma unroll
        for (int nt = 0; nt < 16; nt++) {
            o[nt][0] *= cor0; o[nt][1] *= cor0;
            o[nt][2] *= cor1; o[nt][3] *= cor1;
        }

        // ---- O += P @ V : P frags built in-register from S frags ----
#pragma unroll
        for (int kk = 0; kk < 4; kk++) {
            uint32_t ah[4], al[4];
            {
                float v0 = s[2 * kk][0],     v1 = s[2 * kk][1];
                float v2 = s[2 * kk][2],     v3 = s[2 * kk][3];
                float w0 = s[2 * kk + 1][0], w1 = s[2 * kk + 1][1];
                float w2 = s[2 * kk + 1][2], w3 = s[2 * kk + 1][3];
                ah[0] = pack_bf2(v0, v1); ah[1] = pack_bf2(v2, v3);
                ah[2] = pack_bf2(w0, w1); ah[3] = pack_bf2(w2, w3);
                al[0] = pack_bf2(v0 - __uint_as_float(ah[0] << 16),
                                 v1 - __uint_as_float(ah[0] & 0xFFFF0000u));
                al[1] = pack_bf2(v2 - __uint_as_float(ah[1] << 16),
                                 v3 - __uint_as_float(ah[1] & 0xFFFF0000u));
                al[2] = pack_bf2(w0 - __uint_as_float(ah[2] << 16),
                                 w1 - __uint_as_float(ah[2] & 0xFFFF0000u));
                al[3] = pack_bf2(w2 - __uint_as_float(ah[3] << 16),
                                 w3 - __uint_as_float(ah[3] & 0xFFFF0000u));
            }
#pragma unroll
            for (int nb = 0; nb < 8; nb++) {
                uint32_t vh4[4], vl4[4];
                uint32_t vaddr = smb + A_VH + (kk * 16 + l8 * 8 + rin) * AQLD
                               + (nb * 16 + l16 * 8) * 2;
                LDM_X4T(vh4, vaddr);
                LDM_X4T(vl4, vaddr + ATILE);
#pragma unroll
                for (int hf = 0; hf < 2; hf++) {
                    mma_bf16(o[nb * 2 + hf], ah, &vh4[hf * 2]);
                    mma_bf16(o[nb * 2 + hf], ah, &vl4[hf * 2]);
                    mma_bf16(o[nb * 2 + hf], al, &vh4[hf * 2]);
                }
            }
        }
    }

    // ---- epilogue: normalize + bf16-split store for the O-projection ----
    float inv0 = 1.f / l0, inv1 = 1.f / l1;
    const size_t r0 = bbase + q0 + wid * 16 + (lane >> 2);
    const int gc = h * HD + 2 * (lane & 3);
#pragma unroll
    for (int nt = 0; nt < 16; nt++) {
        int col = gc + nt * 8;
        float v0 = o[nt][0] * inv0, v1 = o[nt][1] * inv0;
        uint32_t hh = pack_bf2(v0, v1);
        uint32_t ll = pack_bf2(v0 - __uint_as_float(hh << 16),
                               v1 - __uint_as_float(hh & 0xFFFF0000u));
        *(uint32_t*)(g_attnb_hi + r0 * HIDD + col) = hh;
        *(uint32_t*)(g_attnb_lo + r0 * HIDD + col) = ll;
        float v2 = o[nt][2] * inv1, v3 = o[nt][3] * inv1;
        hh = pack_bf2(v2, v3);
        ll = pack_bf2(v2 - __uint_as_float(hh << 16),
                      v3 - __uint_as_float(hh & 0xFFFF0000u));
        *(uint32_t*)(g_attnb_hi + (r0 + 8) * HIDD + col) = hh;
        *(uint32_t*)(g_attnb_lo + (r0 + 8) * HIDD + col) = ll;
    }
}

// ---------------------------------------------------------------------------
extern "C" void kernel_launch(void* const* d_in, const int* in_sizes, int n_in,
                              void* d_out, int out_size)
{
    const float* hidden = (const float*)d_in[0];
    const float* fcos   = (const float*)d_in[1];
    const float* fsin   = (const float*)d_in[2];
    const float* w_qkv  = (const float*)d_in[6];
    const float* w_o    = (const float*)d_in[7];
    float* out = (float*)d_out;

    float* qkv_f;
    __nv_bfloat16 *hid_hi, *hid_lo, *wqkv_hi, *wqkv_lo, *wo_hi, *wo_lo;
    __nv_bfloat16 *attn_hi, *attn_lo;
    cudaGetSymbolAddress((void**)&qkv_f,   g_qkv);
    cudaGetSymbolAddress((void**)&hid_hi,  g_hid_hi);
    cudaGetSymbolAddress((void**)&hid_lo,  g_hid_lo);
    cudaGetSymbolAddress((void**)&wqkv_hi, g_wqkv_hi);
    cudaGetSymbolAddress((void**)&wqkv_lo, g_wqkv_lo);
    cudaGetSymbolAddress((void**)&wo_hi,   g_wo_hi);
    cudaGetSymbolAddress((void**)&wo_lo,   g_wo_lo);
    cudaGetSymbolAddress((void**)&attn_hi, g_attnb_hi);
    cudaGetSymbolAddress((void**)&attn_lo, g_attnb_lo);

    cudaFuncSetAttribute(gemm_pre_kernel,
                         cudaFuncAttributeMaxDynamicSharedMemorySize, GT_SMEM);
    cudaFuncSetAttribute(attn_kernel,
                         cudaFuncAttributeMaxDynamicSharedMemorySize, ATT_SMEM);

    const int M = BB * TT;  // 4096

    // 0) split fp32 operands into bf16 hi/lo
    split_kernel<<<8192, 256>>>(hidden, hid_hi, hid_lo, (BB * TT * HIDD) / 4);
    split_kernel<<<8192, 256>>>(w_qkv, wqkv_hi, wqkv_lo, (QKVW * HIDD) / 4);
    split_kernel<<<4096, 256>>>(w_o, wo_hi, wo_lo, (HIDD * HIDD) / 4);

    // 1) QKV projection -> g_qkv fp32
    gemm_pre_kernel<<<dim3(QKVW / 128, M / 128), 256, GT_SMEM>>>(
        hid_hi, hid_lo, wqkv_hi, wqkv_lo, qkv_f, M, QKVW, HIDD);

    // 2) RoPE + scale-fold + bf16 split -> g_qkvb
    ropesplit_kernel<<<dim3(BB * TT, 8), 128>>>(fcos, fsin);

    // 3) causal GQA attention (tensor cores) -> g_attnb bf16 hi/lo
    attn_kernel<<<dim3(TT / 64, NH, BB), 128, ATT_SMEM>>>();

    // 4) output projection -> d_out fp32
    gemm_pre_kernel<<<dim3(HIDD / 128, M / 128), 256, GT_SMEM>>>(
        attn_hi, attn_lo, wo_hi, wo_lo, out, M, HIDD, HIDD);
}

// round 7
// speedup vs baseline: 1.3547x; 1.3547x over previous
#include <cuda_runtime.h>
#include <cuda_fp16.h>
#include <math.h>
#include <stdint.h>

// Problem constants
#define BB 2
#define TT 2048
#define HIDD 2048
#define NH 16
#define NKV 8
#define HD 128
#define QKVW 4096   // (NH + 2*NKV) * HD
#define KOFF 2048   // NH*HD
#define VOFF 3072   // NH*HD + NKV*HD
#define ATT_SCALE 0.08838834764831845f  // 128^-0.5

// Scratch (allocation-free rule: __device__ globals)
__device__ float  g_qkv[(size_t)BB * TT * QKVW];          // 64 MB fp32
__device__ __half g_hid[(size_t)BB * TT * HIDD];          // activations, single fp16
__device__ __half g_wqkv_hi[(size_t)QKVW * HIDD];
__device__ __half g_wqkv_lo[(size_t)QKVW * HIDD];
__device__ __half g_wo_hi[(size_t)HIDD * HIDD];
__device__ __half g_wo_lo[(size_t)HIDD * HIDD];
__device__ __half g_qkvb_hi[(size_t)BB * TT * QKVW];
__device__ __half g_qkvb_lo[(size_t)BB * TT * QKVW];
__device__ __half g_attnb[(size_t)BB * TT * HIDD];        // attn out, single fp16

// ---------------------------------------------------------------------------
// Helpers (arch-stable PTX: cp.async + ldmatrix + mma.sync, sm_80 level)
// ---------------------------------------------------------------------------
__device__ __forceinline__ uint32_t smem_u32(const void* p) {
    uint32_t a;
    asm("{ .reg .u64 t; cvta.to.shared.u64 t, %1; cvt.u32.u64 %0, t; }"
        : "=r"(a) : "l"(p));
    return a;
}

// pack two f32 -> f16x2 (lo half = x, hi half = y)
__device__ __forceinline__ uint32_t pack_hf2(float x, float y) {
    __half2 h = __floats2half2_rn(x, y);
    return *reinterpret_cast<uint32_t*>(&h);
}
__device__ __forceinline__ float2 unpk_hf2(uint32_t u) {
    __half2 h = *reinterpret_cast<__half2*>(&u);
    return __half22float2(h);
}

#define LDM_X4(r, a)                                                            \
    asm volatile("ldmatrix.sync.aligned.m8n8.x4.shared.b16 {%0,%1,%2,%3}, [%4];"\
        : "=r"((r)[0]), "=r"((r)[1]), "=r"((r)[2]), "=r"((r)[3]) : "r"(a))

#define LDM_X4T(r, a)                                                           \
    asm volatile("ldmatrix.sync.aligned.m8n8.x4.trans.shared.b16 "              \
                 "{%0,%1,%2,%3}, [%4];"                                         \
        : "=r"((r)[0]), "=r"((r)[1]), "=r"((r)[2]), "=r"((r)[3]) : "r"(a))

__device__ __forceinline__ void mma_f16(float* d, const uint32_t* a, const uint32_t* b) {
    asm volatile(
        "mma.sync.aligned.m16n8k16.row.col.f32.f16.f16.f32 "
        "{%0,%1,%2,%3}, {%4,%5,%6,%7}, {%8,%9}, {%0,%1,%2,%3};"
        : "+f"(d[0]), "+f"(d[1]), "+f"(d[2]), "+f"(d[3])
        : "r"(a[0]), "r"(a[1]), "r"(a[2]), "r"(a[3]), "r"(b[0]), "r"(b[1]));
}

#define CP_A16(dst, src)                                                        \
    asm volatile("cp.async.cg.shared.global [%0], [%1], 16;"                    \
        :: "r"(dst), "l"(src))
#define CP_COMMIT() asm volatile("cp.async.commit_group;" ::: "memory")
#define CP_WAIT(n)  asm volatile("cp.async.wait_group %0;" :: "n"(n) : "memory")

// ---------------------------------------------------------------------------
// split2: fp32 -> fp16 hi + fp16 lo  (x ~= hi + lo)
// ---------------------------------------------------------------------------
__global__ void split2_kernel(const float* __restrict__ src,
                              __half* __restrict__ hi,
                              __half* __restrict__ lo, int n4)
{
    int i = blockIdx.x * blockDim.x + threadIdx.x;
    if (i >= n4) return;
    float4 v = ((const float4*)src)[i];
    uint32_t h0 = pack_hf2(v.x, v.y), h1 = pack_hf2(v.z, v.w);
    float2 f0 = unpk_hf2(h0), f1 = unpk_hf2(h1);
    ((uint2*)hi)[i] = make_uint2(h0, h1);
    ((uint2*)lo)[i] = make_uint2(pack_hf2(v.x - f0.x, v.y - f0.y),
                                 pack_hf2(v.z - f1.x, v.w - f1.y));
}

// split1: fp32 -> fp16 (round-to-nearest)
__global__ void split1_kernel(const float* __restrict__ src,
                              __half* __restrict__ dst, int n4)
{
    int i = blockIdx.x * blockDim.x + threadIdx.x;
    if (i >= n4) return;
    float4 v = ((const float4*)src)[i];
    ((uint2*)dst)[i] = make_uint2(pack_hf2(v.x, v.y), pack_hf2(v.z, v.w));
}

// ---------------------------------------------------------------------------
// RoPE (Q,K) + fp16 hi/lo split of the whole QKV row; Q pre-scaled by
// ATT_SCALE (folded out of the attention score computation).
// ---------------------------------------------------------------------------
__global__ void ropesplit_kernel(const float* __restrict__ cosT,
                                 const float* __restrict__ sinT)
{
    const int bt   = blockIdx.x;
    const int t    = bt & (TT - 1);
    const int slot = blockIdx.y * blockDim.x + threadIdx.x;   // 0..1023
    const int col  = slot * 4;
    const float* row = g_qkv + (size_t)bt * QKVW;
    float4 v = *(const float4*)(row + col);

    if (col < VOFF) {   // Q or K head: rope
        int d  = col & (HD - 1);
        int dd = d & 63;
        float4 c = *(const float4*)(cosT + t * 64 + dd);
        float4 s = *(const float4*)(sinT + t * 64 + dd);
        if (d < 64) {
            float4 x2 = *(const float4*)(row + col + 64);
            v.x = v.x * c.x - x2.x * s.x;
            v.y = v.y * c.y - x2.y * s.y;
            v.z = v.z * c.z - x2.z * s.z;
            v.w = v.w * c.w - x2.w * s.w;
        } else {
            float4 x1 = *(const float4*)(row + col - 64);
            v.x = x1.x * s.x + v.x * c.x;
            v.y = x1.y * s.y + v.y * c.y;
            v.z = x1.z * s.z + v.z * c.z;
            v.w = x1.w * s.w + v.w * c.w;
        }
        if (col < KOFF) {   // Q: fold attention scale
            v.x *= ATT_SCALE; v.y *= ATT_SCALE; v.z *= ATT_SCALE; v.w *= ATT_SCALE;
        }
    }

    uint32_t h0 = pack_hf2(v.x, v.y), h1 = pack_hf2(v.z, v.w);
    float2 f0 = unpk_hf2(h0), f1 = unpk_hf2(h1);
    size_t o = (size_t)bt * (QKVW / 4) + slot;
    ((uint2*)g_qkvb_hi)[o] = make_uint2(h0, h1);
    ((uint2*)g_qkvb_lo)[o] = make_uint2(pack_hf2(v.x - f0.x, v.y - f0.y),
                                        pack_hf2(v.z - f1.x, v.w - f1.y));
}

// ---------------------------------------------------------------------------
// Tensor-core NT GEMM, asymmetric fp16 2-term split:
//   C[M,N] = A_f16[M,K] @ (Bh+Bl)[N,K]^T, fp32 accumulate, 2 MMA products.
// CTA 128x128, BK=32, 8 warps (4m x 2n -> 32x64 warp tile).
// 3-stage cp.async pipeline, 2 CTAs/SM (<=128 regs, 90 KB smem).
// SMEM rows: 32 fp16 + 8 pad = 80 B (conflict-free ldmatrix).
// ---------------------------------------------------------------------------
#define GT_BUF  10240                // one 128x32 fp16 tile (rows of 80 B)
#define GT_STG  (3 * GT_BUF)         // A, Bh, Bl = 30720
#define GT_SMEM (3 * GT_STG)         // 3 stages = 92160

#define GT_ISSUE(c)                                                            \
    do {                                                                       \
        uint32_t sb_ = smb + ((c) % 3) * GT_STG;                               \
        _Pragma("unroll")                                                      \
        for (int i_ = 0; i_ < 6; i_++) {   /* 3 bufs x 512 chunks / 256 thr */ \
            const int bu_ = i_ >> 1;                                           \
            int w_ = (i_ & 1) * 256 + tid;                                     \
            int r_ = w_ >> 2, ch_ = w_ & 3;                                    \
            CP_A16(sb_ + bu_ * GT_BUF + r_ * 80 + ch_ * 16,                    \
                   tb[bu_] + (size_t)r_ * K + (c) * 32 + ch_ * 8);             \
        }                                                                      \
    } while (0)

__global__ void __launch_bounds__(256, 2) gemm_pre_kernel(
    const __half* __restrict__ A,
    const __half* __restrict__ Bh, const __half* __restrict__ Bl,
    float* __restrict__ C, int M, int N, int K)
{
    extern __shared__ char sm[];
    const uint32_t smb = smem_u32(sm);
    const int tid = threadIdx.x;
    const int wid = tid >> 5, lane = tid & 31;
    const int m0 = blockIdx.y * 128, n0 = blockIdx.x * 128;
    const int wm = wid & 3, wn = wid >> 2;          // 4m x 2n, 32x64 each
    const int quad = lane >> 3, rin = lane & 7;

    const __half* tb[3] = {
        A + (size_t)m0 * K, Bh + (size_t)n0 * K, Bl + (size_t)n0 * K };
    const int NC = K / 32;

    float acc[2][8][4];
#pragma unroll
    for (int i = 0; i < 2; i++)
#pragma unroll
        for (int j = 0; j < 8; j++)
#pragma unroll
            for (int u = 0; u < 4; u++) acc[i][j][u] = 0.f;

    GT_ISSUE(0); CP_COMMIT();
    GT_ISSUE(1); CP_COMMIT();
    GT_ISSUE(2); CP_COMMIT();

    for (int c = 0; c < NC; c++) {
        CP_WAIT(2);
        __syncthreads();

        const uint32_t aBase = smb + (c % 3) * GT_STG;
        const uint32_t bBase = aBase + GT_BUF;
#pragma unroll
        for (int ks = 0; ks < 2; ks++) {
            const int k0 = ks * 16;
            uint32_t af[2][4];
#pragma unroll
            for (int mt = 0; mt < 2; mt++) {
                int row = wm * 32 + mt * 16 + (quad & 1) * 8 + rin;
                int col = k0 + (quad >> 1) * 8;
                LDM_X4(af[mt], aBase + row * 80 + col * 2);
            }
#pragma unroll
            for (int nb = 0; nb < 4; nb++) {
                uint32_t bh4[4], bl4[4];
                int rowb = wn * 64 + nb * 16 + (quad >> 1) * 8 + rin;
                int colb = k0 + (quad & 1) * 8;
                uint32_t bd = bBase + rowb * 80 + colb * 2;
                LDM_X4(bh4, bd);
                LDM_X4(bl4, bd + GT_BUF);
#pragma unroll
                for (int mt = 0; mt < 2; mt++)
#pragma unroll
                    for (int hf = 0; hf < 2; hf++) {
                        mma_f16(acc[mt][nb * 2 + hf], af[mt], &bh4[hf * 2]);
                        mma_f16(acc[mt][nb * 2 + hf], af[mt], &bl4[hf * 2]);
                    }
            }
        }

        __syncthreads();                 // stage (c%3) fully consumed
        if (c + 3 < NC) GT_ISSUE(c + 3);
        CP_COMMIT();
    }

    const int lr = lane >> 2;
    const int lc = (lane & 3) * 2;
#pragma unroll
    for (int mt = 0; mt < 2; mt++)
#pragma unroll
        for (int nt = 0; nt < 8; nt++) {
            int row = m0 + wm * 32 + mt * 16 + lr;
            int col = n0 + wn * 64 + nt * 8 + lc;
            *(float2*)(C + (size_t)row * N + col) =
                make_float2(acc[mt][nt][0], acc[mt][nt][1]);
            *(float2*)(C + (size_t)(row + 8) * N + col) =
                make_float2(acc[mt][nt][2], acc[mt][nt][3]);
        }
}

// ---------------------------------------------------------------------------
// Tensor-core causal GQA flash attention (fp16 asymmetric split, fp32 accum).
// S = Qh @ (Kh+Kl)^T (2 MMAs); O += Ph @ (Vh+Vl) (2 MMAs).
// CTA: 64 Q rows x (head, batch); 4 warps, each warp owns 16 Q rows.
// SMEM tiles (64 rows x 272 B): Qh, Kh, Kl, Vh, Vl.
// ---------------------------------------------------------------------------
#define AQLD  272
#define ATILE 17408                 // 64 rows x 272 B
#define A_KH  (1 * ATILE)
#define A_VH  (3 * ATILE)
#define ATT_SMEM (5 * ATILE)        // 87040 B

__global__ void __launch_bounds__(128, 2) attn_kernel()
{
    extern __shared__ char sm[];
    const uint32_t smb = smem_u32(sm);
    const int tid = threadIdx.x;
    const int wid = tid >> 5, lane = tid & 31;
    const int q0 = blockIdx.x * 64;
    const int h = blockIdx.y, b = blockIdx.z;
    const int khh = h >> 1;                 // GQA: n_rep = 2

    const int l8  = (lane >> 3) & 1;
    const int l16 = lane >> 4;
    const int rin = lane & 7;

    // ---- load Q tile (hi only) once (cp.async) ----
    {
        const __half* qh = g_qkvb_hi + ((size_t)(b * TT + q0)) * QKVW + h * HD;
#pragma unroll
        for (int i = 0; i < 8; i++) {
            int w = i * 128 + tid;
            int r = w >> 4, ch = w & 15;
            CP_A16(smb + r * AQLD + ch * 16, qh + (size_t)r * QKVW + ch * 8);
        }
        CP_COMMIT();
    }

    float o[16][4];
#pragma unroll
    for (int i = 0; i < 16; i++)
#pragma unroll
        for (int u = 0; u < 4; u++) o[i][u] = 0.f;
    float m0r = -1e30f, m1r = -1e30f, l0 = 0.f, l1 = 0.f;

    const size_t bbase = (size_t)(b * TT);
    const int ntiles = (q0 >> 6) + 1;

    for (int jt = 0; jt < ntiles; jt++) {
        const int kb = jt << 6;
        __syncthreads();   // everyone done reading previous K/V tiles

        // ---- load K,V hi/lo tiles ----
        {
            const size_t rb = (bbase + kb) * QKVW;
            const __half* s0 = g_qkvb_hi + rb + KOFF + khh * HD;
            const __half* s1 = g_qkvb_lo + rb + KOFF + khh * HD;
            const __half* s2 = g_qkvb_hi + rb + VOFF + khh * HD;
            const __half* s3 = g_qkvb_lo + rb + VOFF + khh * HD;
#pragma unroll
            for (int i = 0; i < 32; i++) {
                const int t = i >> 3;
                int w = (i & 7) * 128 + tid;
                int r = w >> 4, ch = w & 15;
                const __half* src =
                    (t == 0 ? s0 : t == 1 ? s1 : t == 2 ? s2 : s3)
                    + (size_t)r * QKVW + ch * 8;
                CP_A16(smb + A_KH + t * ATILE + r * AQLD + ch * 16, src);
            }
            CP_COMMIT();
        }
        CP_WAIT(0);
        __syncthreads();

        // ---- S = Qh @ (Kh + Kl)^T  (Q pre-scaled by ATT_SCALE) ----
        float s[8][4];
#pragma unroll
        for (int i = 0; i < 8; i++)
#pragma unroll
            for (int u = 0; u < 4; u++) s[i][u] = 0.f;

#pragma unroll
        for (int ks = 0; ks < 8; ks++) {
            const int k0 = ks * 16;
            uint32_t aq[4];
            LDM_X4(aq, smb + (wid * 16 + l8 * 8 + rin) * AQLD + (k0 + l16 * 8) * 2);
#pragma unroll
            for (int nb = 0; nb < 4; nb++) {
                uint32_t kh4[4], kl4[4];
                uint32_t baddr = smb + A_KH + (nb * 16 + l16 * 8 + rin) * AQLD
                               + (k0 + l8 * 8) * 2;
                LDM_X4(kh4, baddr);
                LDM_X4(kl4, baddr + ATILE);
#pragma unroll
                for (int hf = 0; hf < 2; hf++) {
                    mma_f16(s[nb * 2 + hf], aq, &kh4[hf * 2]);
                    mma_f16(s[nb * 2 + hf], aq, &kl4[hf * 2]);
                }
            }
        }

        // ---- causal mask on the diagonal tile ----
        if (kb == q0) {
            const int r0l = wid * 16 + (lane >> 2);
#pragma unroll
            for (int nt = 0; nt < 8; nt++) {
                int c0 = nt * 8 + 2 * (lane & 3);
                if (c0     > r0l)     s[nt][0] = -1e30f;
                if (c0 + 1 > r0l)     s[nt][1] = -1e30f;
                if (c0     > r0l + 8) s[nt][2] = -1e30f;
                if (c0 + 1 > r0l + 8) s[nt][3] = -1e30f;
            }
        }

        // ---- register online softmax (rows lr and lr+8) ----
        float tm0 = -1e30f, tm1 = -1e30f;
#pragma unroll
        for (int nt = 0; nt < 8; nt++) {
            tm0 = fmaxf(tm0, fmaxf(s[nt][0], s[nt][1]));
            tm1 = fmaxf(tm1, fmaxf(s[nt][2], s[nt][3]));
        }
        tm0 = fmaxf(tm0, __shfl_xor_sync(0xffffffffu, tm0, 1));
        tm0 = fmaxf(tm0, __shfl_xor_sync(0xffffffffu, tm0, 2));
        tm1 = fmaxf(tm1, __shfl_xor_sync(0xffffffffu, tm1, 1));
        tm1 = fmaxf(tm1, __shfl_xor_sync(0xffffffffu, tm1, 2));
        float nm0 = fmaxf(m0r, tm0), nm1 = fmaxf(m1r, tm1);
        float cor0 = __expf(m0r - nm0), cor1 = __expf(m1r - nm1);
        m0r = nm0; m1r = nm1;

        float sum0 = 0.f, sum1 = 0.f;
#pragma unroll
        for (int nt = 0; nt < 8; nt++) {
            s[nt][0] = __expf(s[nt][0] - nm0);
            s[nt][1] = __expf(s[nt][1] - nm0);
            s[nt][2] = __expf(s[nt][2] - nm1);
            s[nt][3] = __expf(s[nt][3] - nm1);
            sum0 += s[nt][0] + s[nt][1];
            sum1 += s[nt][2] + s[nt][3];
        }
        sum0 += __shfl_xor_sync(0xffffffffu, sum0, 1);
        sum0 += __shfl_xor_sync(0xffffffffu, sum0, 2);
        sum1 += __shfl_xor_sync(0xffffffffu, sum1, 1);
        sum1 += __shfl_xor_sync(0xffffffffu, sum1, 2);
        l0 = l0 * cor0 + sum0;
        l1 = l1 * cor1 + sum1;

#pragma unroll
        for (int nt = 0; nt < 16; nt++) {
            o[nt][0] *= cor0; o[nt][1] *= cor0;
            o[nt][2] *= cor1; o[nt][3] *= cor1;
        }

        // ---- O += Ph @ (Vh + Vl) : P frags built in-register (fp16) ----
#pragma unroll
        for (int kk = 0; kk < 4; kk++) {
            uint32_t ah[4];
            ah[0] = pack_hf2(s[2 * kk][0],     s[2 * kk][1]);
            ah[1] = pack_hf2(s[2 * kk][2],     s[2 * kk][3]);
            ah[2] = pack_hf2(s[2 * kk + 1][0], s[2 * kk + 1][1]);
            ah[3] = pack_hf2(s[2 * kk + 1][2], s[2 * kk + 1][3]);
#pragma unroll
            for (int nb = 0; nb < 8; nb++) {
                uint32_t vh4[4], vl4[4];
                uint32_t vaddr = smb + A_VH + (kk * 16 + l8 * 8 + rin) * AQLD
                               + (nb * 16 + l16 * 8) * 2;
                LDM_X4T(vh4, vaddr);
                LDM_X4T(vl4, vaddr + ATILE);
#pragma unroll
                for (int hf = 0; hf < 2; hf++) {
                    mma_f16(o[nb * 2 + hf], ah, &vh4[hf * 2]);
                    mma_f16(o[nb * 2 + hf], ah, &vl4[hf * 2]);
                }
            }
        }
    }

    // ---- epilogue: normalize + fp16 store for the O-projection ----
    float inv0 = 1.f / l0, inv1 = 1.f / l1;
    const size_t r0 = bbase + q0 + wid * 16 + (lane >> 2);
    const int gc = h * HD + 2 * (lane & 3);
#pragma unroll
    for (int nt = 0; nt < 16; nt++) {
        int col = gc + nt * 8;
        *(uint32_t*)(g_attnb + r0 * HIDD + col) =
            pack_hf2(o[nt][0] * inv0, o[nt][1] * inv0);
        *(uint32_t*)(g_attnb + (r0 + 8) * HIDD + col) =
            pack_hf2(o[nt][2] * inv1, o[nt][3] * inv1);
    }
}

// ---------------------------------------------------------------------------
extern "C" void kernel_launch(void* const* d_in, const int* in_sizes, int n_in,
                              void* d_out, int out_size)
{
    const float* hidden = (const float*)d_in[0];
    const float* fcos   = (const float*)d_in[1];
    const float* fsin   = (const float*)d_in[2];
    const float* w_qkv  = (const float*)d_in[6];
    const float* w_o    = (const float*)d_in[7];
    float* out = (float*)d_out;

    float* qkv_f;
    __half *hid, *wqkv_hi, *wqkv_lo, *wo_hi, *wo_lo, *attnb;
    cudaGetSymbolAddress((void**)&qkv_f,   g_qkv);
    cudaGetSymbolAddress((void**)&hid,     g_hid);
    cudaGetSymbolAddress((void**)&wqkv_hi, g_wqkv_hi);
    cudaGetSymbolAddress((void**)&wqkv_lo, g_wqkv_lo);
    cudaGetSymbolAddress((void**)&wo_hi,   g_wo_hi);
    cudaGetSymbolAddress((void**)&wo_lo,   g_wo_lo);
    cudaGetSymbolAddress((void**)&attnb,   g_attnb);

    cudaFuncSetAttribute(gemm_pre_kernel,
                         cudaFuncAttributeMaxDynamicSharedMemorySize, GT_SMEM);
    cudaFuncSetAttribute(attn_kernel,
                         cudaFuncAttributeMaxDynamicSharedMemorySize, ATT_SMEM);

    const int M = BB * TT;  // 4096

    // 0) convert operands: activations fp16, weights fp16 hi/lo
    split1_kernel<<<8192, 256>>>(hidden, hid, (BB * TT * HIDD) / 4);
    split2_kernel<<<8192, 256>>>(w_qkv, wqkv_hi, wqkv_lo, (QKVW * HIDD) / 4);
    split2_kernel<<<4096, 256>>>(w_o, wo_hi, wo_lo, (HIDD * HIDD) / 4);

    // 1) QKV projection -> g_qkv fp32
    gemm_pre_kernel<<<dim3(QKVW / 128, M / 128), 256, GT_SMEM>>>(
        hid, wqkv_hi, wqkv_lo, qkv_f, M, QKVW, HIDD);

    // 2) RoPE + scale-fold + fp16 hi/lo split -> g_qkvb
    ropesplit_kernel<<<dim3(BB * TT, 8), 128>>>(fcos, fsin);

    // 3) causal GQA attention (tensor cores) -> g_attnb fp16
    attn_kernel<<<dim3(TT / 64, NH, BB), 128, ATT_SMEM>>>();

    // 4) output projection -> d_out fp32
    gemm_pre_kernel<<<dim3(HIDD / 128, M / 128), 256, GT_SMEM>>>(
        attnb, wo_hi, wo_lo, out, M, HIDD, HIDD);
}

// round 8
// speedup vs baseline: 2.2691x; 1.6750x over previous
#include <cuda_runtime.h>
#include <cuda_fp16.h>
#include <math.h>
#include <stdint.h>

// Problem constants
#define BB 2
#define TT 2048
#define HIDD 2048
#define NH 16
#define NKV 8
#define HD 128
#define QKVW 4096   // (NH + 2*NKV) * HD
#define KOFF 2048   // NH*HD
#define VOFF 3072   // NH*HD + NKV*HD
#define ATT_SCALE 0.08838834764831845f  // 128^-0.5

// Scratch (allocation-free rule: __device__ globals)
__device__ float  g_qkv[(size_t)BB * TT * QKVW];          // 64 MB fp32
__device__ __half g_hid[(size_t)BB * TT * HIDD];          // activations fp16
__device__ __half g_wqkv[(size_t)QKVW * HIDD];
__device__ __half g_wo[(size_t)HIDD * HIDD];
__device__ __half g_qkvb[(size_t)BB * TT * QKVW];         // roped qkv fp16
__device__ __half g_attnb[(size_t)BB * TT * HIDD];        // attn out fp16

// ---------------------------------------------------------------------------
// Helpers (arch-stable PTX: cp.async + ldmatrix + mma.sync, sm_80 level)
// ---------------------------------------------------------------------------
__device__ __forceinline__ uint32_t smem_u32(const void* p) {
    uint32_t a;
    asm("{ .reg .u64 t; cvta.to.shared.u64 t, %1; cvt.u32.u64 %0, t; }"
        : "=r"(a) : "l"(p));
    return a;
}

// pack two f32 -> f16x2 (lo half = x, hi half = y)
__device__ __forceinline__ uint32_t pack_hf2(float x, float y) {
    __half2 h = __floats2half2_rn(x, y);
    return *reinterpret_cast<uint32_t*>(&h);
}

#define LDM_X4(r, a)                                                            \
    asm volatile("ldmatrix.sync.aligned.m8n8.x4.shared.b16 {%0,%1,%2,%3}, [%4];"\
        : "=r"((r)[0]), "=r"((r)[1]), "=r"((r)[2]), "=r"((r)[3]) : "r"(a))

#define LDM_X4T(r, a)                                                           \
    asm volatile("ldmatrix.sync.aligned.m8n8.x4.trans.shared.b16 "              \
                 "{%0,%1,%2,%3}, [%4];"                                         \
        : "=r"((r)[0]), "=r"((r)[1]), "=r"((r)[2]), "=r"((r)[3]) : "r"(a))

__device__ __forceinline__ void mma_f16(float* d, const uint32_t* a, const uint32_t* b) {
    asm volatile(
        "mma.sync.aligned.m16n8k16.row.col.f32.f16.f16.f32 "
        "{%0,%1,%2,%3}, {%4,%5,%6,%7}, {%8,%9}, {%0,%1,%2,%3};"
        : "+f"(d[0]), "+f"(d[1]), "+f"(d[2]), "+f"(d[3])
        : "r"(a[0]), "r"(a[1]), "r"(a[2]), "r"(a[3]), "r"(b[0]), "r"(b[1]));
}

#define CP_A16(dst, src)                                                        \
    asm volatile("cp.async.cg.shared.global [%0], [%1], 16;"                    \
        :: "r"(dst), "l"(src))
#define CP_COMMIT() asm volatile("cp.async.commit_group;" ::: "memory")
#define CP_WAIT(n)  asm volatile("cp.async.wait_group %0;" :: "n"(n) : "memory")

// ---------------------------------------------------------------------------
// fp32 -> fp16 (round-to-nearest), vectorized
// ---------------------------------------------------------------------------
__global__ void split1_kernel(const float* __restrict__ src,
                              __half* __restrict__ dst, int n4)
{
    int i = blockIdx.x * blockDim.x + threadIdx.x;
    if (i >= n4) return;
    float4 v = ((const float4*)src)[i];
    ((uint2*)dst)[i] = make_uint2(pack_hf2(v.x, v.y), pack_hf2(v.z, v.w));
}

// ---------------------------------------------------------------------------
// RoPE (Q,K) + fp16 convert of the whole QKV row; Q pre-scaled by ATT_SCALE.
// ---------------------------------------------------------------------------
__global__ void ropesplit_kernel(const float* __restrict__ cosT,
                                 const float* __restrict__ sinT)
{
    const int bt   = blockIdx.x;
    const int t    = bt & (TT - 1);
    const int slot = blockIdx.y * blockDim.x + threadIdx.x;   // 0..1023
    const int col  = slot * 4;
    const float* row = g_qkv + (size_t)bt * QKVW;
    float4 v = *(const float4*)(row + col);

    if (col < VOFF) {   // Q or K head: rope
        int d  = col & (HD - 1);
        int dd = d & 63;
        float4 c = *(const float4*)(cosT + t * 64 + dd);
        float4 s = *(const float4*)(sinT + t * 64 + dd);
        if (d < 64) {
            float4 x2 = *(const float4*)(row + col + 64);
            v.x = v.x * c.x - x2.x * s.x;
            v.y = v.y * c.y - x2.y * s.y;
            v.z = v.z * c.z - x2.z * s.z;
            v.w = v.w * c.w - x2.w * s.w;
        } else {
            float4 x1 = *(const float4*)(row + col - 64);
            v.x = x1.x * s.x + v.x * c.x;
            v.y = x1.y * s.y + v.y * c.y;
            v.z = x1.z * s.z + v.z * c.z;
            v.w = x1.w * s.w + v.w * c.w;
        }
        if (col < KOFF) {   // Q: fold attention scale
            v.x *= ATT_SCALE; v.y *= ATT_SCALE; v.z *= ATT_SCALE; v.w *= ATT_SCALE;
        }
    }

    size_t o = (size_t)bt * (QKVW / 4) + slot;
    ((uint2*)g_qkvb)[o] = make_uint2(pack_hf2(v.x, v.y), pack_hf2(v.z, v.w));
}

// ---------------------------------------------------------------------------
// Tensor-core NT GEMM, single fp16: C[M,N] = A[M,K] @ B[N,K]^T, fp32 accum.
// CTA 128x128, BK=32, 8 warps (4m x 2n -> 32x64 warp tile).
// 3-stage cp.async pipeline, 2 CTAs/SM. SMEM rows: 32 fp16 + 8 pad = 80 B.
// ---------------------------------------------------------------------------
#define GT_BUF  10240                // one 128x32 fp16 tile (rows of 80 B)
#define GT_STG  (2 * GT_BUF)         // A, B = 20480
#define GT_SMEM (3 * GT_STG)         // 3 stages = 61440

#define GT_ISSUE(c)                                                            \
    do {                                                                       \
        uint32_t sb_ = smb + ((c) % 3) * GT_STG;                               \
        _Pragma("unroll")                                                      \
        for (int i_ = 0; i_ < 4; i_++) {   /* 2 bufs x 512 chunks / 256 thr */ \
            const int bu_ = i_ >> 1;                                           \
            int w_ = (i_ & 1) * 256 + tid;                                     \
            int r_ = w_ >> 2, ch_ = w_ & 3;                                    \
            CP_A16(sb_ + bu_ * GT_BUF + r_ * 80 + ch_ * 16,                    \
                   tb[bu_] + (size_t)r_ * K + (c) * 32 + ch_ * 8);             \
        }                                                                      \
    } while (0)

__global__ void __launch_bounds__(256, 2) gemm_pre_kernel(
    const __half* __restrict__ A, const __half* __restrict__ B,
    float* __restrict__ C, int M, int N, int K)
{
    extern __shared__ char sm[];
    const uint32_t smb = smem_u32(sm);
    const int tid = threadIdx.x;
    const int wid = tid >> 5, lane = tid & 31;
    const int m0 = blockIdx.y * 128, n0 = blockIdx.x * 128;
    const int wm = wid & 3, wn = wid >> 2;          // 4m x 2n, 32x64 each
    const int quad = lane >> 3, rin = lane & 7;

    const __half* tb[2] = { A + (size_t)m0 * K, B + (size_t)n0 * K };
    const int NC = K / 32;

    float acc[2][8][4];
#pragma unroll
    for (int i = 0; i < 2; i++)
#pragma unroll
        for (int j = 0; j < 8; j++)
#pragma unroll
            for (int u = 0; u < 4; u++) acc[i][j][u] = 0.f;

    GT_ISSUE(0); CP_COMMIT();
    GT_ISSUE(1); CP_COMMIT();
    GT_ISSUE(2); CP_COMMIT();

    for (int c = 0; c < NC; c++) {
        CP_WAIT(2);
        __syncthreads();

        const uint32_t aBase = smb + (c % 3) * GT_STG;
        const uint32_t bBase = aBase + GT_BUF;
#pragma unroll
        for (int ks = 0; ks < 2; ks++) {
            const int k0 = ks * 16;
            uint32_t af[2][4];
#pragma unroll
            for (int mt = 0; mt < 2; mt++) {
                int row = wm * 32 + mt * 16 + (quad & 1) * 8 + rin;
                int col = k0 + (quad >> 1) * 8;
                LDM_X4(af[mt], aBase + row * 80 + col * 2);
            }
#pragma unroll
            for (int nb = 0; nb < 4; nb++) {
                uint32_t b4[4];
                int rowb = wn * 64 + nb * 16 + (quad >> 1) * 8 + rin;
                int colb = k0 + (quad & 1) * 8;
                LDM_X4(b4, bBase + rowb * 80 + colb * 2);
#pragma unroll
                for (int mt = 0; mt < 2; mt++)
#pragma unroll
                    for (int hf = 0; hf < 2; hf++)
                        mma_f16(acc[mt][nb * 2 + hf], af[mt], &b4[hf * 2]);
            }
        }

        __syncthreads();                 // stage (c%3) fully consumed
        if (c + 3 < NC) GT_ISSUE(c + 3);
        CP_COMMIT();
    }

    const int lr = lane >> 2;
    const int lc = (lane & 3) * 2;
#pragma unroll
    for (int mt = 0; mt < 2; mt++)
#pragma unroll
        for (int nt = 0; nt < 8; nt++) {
            int row = m0 + wm * 32 + mt * 16 + lr;
            int col = n0 + wn * 64 + nt * 8 + lc;
            *(float2*)(C + (size_t)row * N + col) =
                make_float2(acc[mt][nt][0], acc[mt][nt][1]);
            *(float2*)(C + (size_t)(row + 8) * N + col) =
                make_float2(acc[mt][nt][2], acc[mt][nt][3]);
        }
}

// ---------------------------------------------------------------------------
// Tensor-core causal GQA flash attention (single fp16, fp32 accum).
// S = Q @ K^T; O += P @ V. CTA: 64 Q rows x (head, batch); 4 warps.
// SMEM tiles (64 rows x 272 B): Q, K, V.
// ---------------------------------------------------------------------------
#define AQLD  272
#define ATILE 17408                 // 64 rows x 272 B
#define ATT_SMEM (3 * ATILE)        // 52224 B

__global__ void __launch_bounds__(128, 3) attn_kernel()
{
    extern __shared__ char sm[];
    const uint32_t smb = smem_u32(sm);
    const int tid = threadIdx.x;
    const int wid = tid >> 5, lane = tid & 31;
    const int q0 = blockIdx.x * 64;
    const int h = blockIdx.y, b = blockIdx.z;
    const int khh = h >> 1;                 // GQA: n_rep = 2

    const int l8  = (lane >> 3) & 1;
    const int l16 = lane >> 4;
    const int rin = lane & 7;

    // ---- load Q tile once (cp.async) ----
    {
        const __half* qh = g_qkvb + ((size_t)(b * TT + q0)) * QKVW + h * HD;
#pragma unroll
        for (int i = 0; i < 8; i++) {
            int w = i * 128 + tid;
            int r = w >> 4, ch = w & 15;
            CP_A16(smb + r * AQLD + ch * 16, qh + (size_t)r * QKVW + ch * 8);
        }
        CP_COMMIT();
    }

    float o[16][4];
#pragma unroll
    for (int i = 0; i < 16; i++)
#pragma unroll
        for (int u = 0; u < 4; u++) o[i][u] = 0.f;
    float m0r = -1e30f, m1r = -1e30f, l0 = 0.f, l1 = 0.f;

    const size_t bbase = (size_t)(b * TT);
    const int ntiles = (q0 >> 6) + 1;

    for (int jt = 0; jt < ntiles; jt++) {
        const int kb = jt << 6;
        __syncthreads();   // everyone done reading previous K/V tiles

        // ---- load K,V tiles ----
        {
            const size_t rb = (bbase + kb) * QKVW;
            const __half* s0 = g_qkvb + rb + KOFF + khh * HD;
            const __half* s1 = g_qkvb + rb + VOFF + khh * HD;
#pragma unroll
            for (int i = 0; i < 16; i++) {
                const int t = i >> 3;
                int w = (i & 7) * 128 + tid;
                int r = w >> 4, ch = w & 15;
                const __half* src = (t ? s1 : s0) + (size_t)r * QKVW + ch * 8;
                CP_A16(smb + (1 + t) * ATILE + r * AQLD + ch * 16, src);
            }
            CP_COMMIT();
        }
        CP_WAIT(0);
        __syncthreads();

        // ---- S = Q @ K^T  (Q pre-scaled by ATT_SCALE) ----
        float s[8][4];
#pragma unroll
        for (int i = 0; i < 8; i++)
#pragma unroll
            for (int u = 0; u < 4; u++) s[i][u] = 0.f;

#pragma unroll
        for (int ks = 0; ks < 8; ks++) {
            const int k0 = ks * 16;
            uint32_t aq[4];
            LDM_X4(aq, smb + (wid * 16 + l8 * 8 + rin) * AQLD + (k0 + l16 * 8) * 2);
#pragma unroll
            for (int nb = 0; nb < 4; nb++) {
                uint32_t k4[4];
                LDM_X4(k4, smb + ATILE + (nb * 16 + l16 * 8 + rin) * AQLD
                           + (k0 + l8 * 8) * 2);
#pragma unroll
                for (int hf = 0; hf < 2; hf++)
                    mma_f16(s[nb * 2 + hf], aq, &k4[hf * 2]);
            }
        }

        // ---- causal mask on the diagonal tile ----
        if (kb == q0) {
            const int r0l = wid * 16 + (lane >> 2);
#pragma unroll
            for (int nt = 0; nt < 8; nt++) {
                int c0 = nt * 8 + 2 * (lane & 3);
                if (c0     > r0l)     s[nt][0] = -1e30f;
                if (c0 + 1 > r0l)     s[nt][1] = -1e30f;
                if (c0     > r0l + 8) s[nt][2] = -1e30f;
                if (c0 + 1 > r0l + 8) s[nt][3] = -1e30f;
            }
        }

        // ---- register online softmax (rows lr and lr+8) ----
        float tm0 = -1e30f, tm1 = -1e30f;
#pragma unroll
        for (int nt = 0; nt < 8; nt++) {
            tm0 = fmaxf(tm0, fmaxf(s[nt][0], s[nt][1]));
            tm1 = fmaxf(tm1, fmaxf(s[nt][2], s[nt][3]));
        }
        tm0 = fmaxf(tm0, __shfl_xor_sync(0xffffffffu, tm0, 1));
        tm0 = fmaxf(tm0, __shfl_xor_sync(0xffffffffu, tm0, 2));
        tm1 = fmaxf(tm1, __shfl_xor_sync(0xffffffffu, tm1, 1));
        tm1 = fmaxf(tm1, __shfl_xor_sync(0xffffffffu, tm1, 2));
        float nm0 = fmaxf(m0r, tm0), nm1 = fmaxf(m1r, tm1);
        float cor0 = __expf(m0r - nm0), cor1 = __expf(m1r - nm1);
        m0r = nm0; m1r = nm1;

        float sum0 = 0.f, sum1 = 0.f;
#pragma unroll
        for (int nt = 0; nt < 8; nt++) {
            s[nt][0] = __expf(s[nt][0] - nm0);
            s[nt][1] = __expf(s[nt][1] - nm0);
            s[nt][2] = __expf(s[nt][2] - nm1);
            s[nt][3] = __expf(s[nt][3] - nm1);
            sum0 += s[nt][0] + s[nt][1];
            sum1 += s[nt][2] + s[nt][3];
        }
        sum0 += __shfl_xor_sync(0xffffffffu, sum0, 1);
        sum0 += __shfl_xor_sync(0xffffffffu, sum0, 2);
        sum1 += __shfl_xor_sync(0xffffffffu, sum1, 1);
        sum1 += __shfl_xor_sync(0xffffffffu, sum1, 2);
        l0 = l0 * cor0 + sum0;
        l1 = l1 * cor1 + sum1;

#pragma unroll
        for (int nt = 0; nt < 16; nt++) {
            o[nt][0] *= cor0; o[nt][1] *= cor0;
            o[nt][2] *= cor1; o[nt][3] *= cor1;
        }

        // ---- O += P @ V : P frags built in-register (fp16) ----
#pragma unroll
        for (int kk = 0; kk < 4; kk++) {
            uint32_t ah[4];
            ah[0] = pack_hf2(s[2 * kk][0],     s[2 * kk][1]);
            ah[1] = pack_hf2(s[2 * kk][2],     s[2 * kk][3]);
            ah[2] = pack_hf2(s[2 * kk + 1][0], s[2 * kk + 1][1]);
            ah[3] = pack_hf2(s[2 * kk + 1][2], s[2 * kk + 1][3]);
#pragma unroll
            for (int nb = 0; nb < 8; nb++) {
                uint32_t v4[4];
                LDM_X4T(v4, smb + 2 * ATILE + (kk * 16 + l8 * 8 + rin) * AQLD
                            + (nb * 16 + l16 * 8) * 2);
#pragma unroll
                for (int hf = 0; hf < 2; hf++)
                    mma_f16(o[nb * 2 + hf], ah, &v4[hf * 2]);
            }
        }
    }

    // ---- epilogue: normalize + fp16 store for the O-projection ----
    float inv0 = 1.f / l0, inv1 = 1.f / l1;
    const size_t r0 = bbase + q0 + wid * 16 + (lane >> 2);
    const int gc = h * HD + 2 * (lane & 3);
#pragma unroll
    for (int nt = 0; nt < 16; nt++) {
        int col = gc + nt * 8;
        *(uint32_t*)(g_attnb + r0 * HIDD + col) =
            pack_hf2(o[nt][0] * inv0, o[nt][1] * inv0);
        *(uint32_t*)(g_attnb + (r0 + 8) * HIDD + col) =
            pack_hf2(o[nt][2] * inv1, o[nt][3] * inv1);
    }
}

// ---------------------------------------------------------------------------
extern "C" void kernel_launch(void* const* d_in, const int* in_sizes, int n_in,
                              void* d_out, int out_size)
{
    const float* hidden = (const float*)d_in[0];
    const float* fcos   = (const float*)d_in[1];
    const float* fsin   = (const float*)d_in[2];
    const float* w_qkv  = (const float*)d_in[6];
    const float* w_o    = (const float*)d_in[7];
    float* out = (float*)d_out;

    float* qkv_f;
    __half *hid, *wqkv, *wo, *attnb;
    cudaGetSymbolAddress((void**)&qkv_f, g_qkv);
    cudaGetSymbolAddress((void**)&hid,   g_hid);
    cudaGetSymbolAddress((void**)&wqkv,  g_wqkv);
    cudaGetSymbolAddress((void**)&wo,    g_wo);
    cudaGetSymbolAddress((void**)&attnb, g_attnb);

    cudaFuncSetAttribute(gemm_pre_kernel,
                         cudaFuncAttributeMaxDynamicSharedMemorySize, GT_SMEM);
    cudaFuncSetAttribute(attn_kernel,
                         cudaFuncAttributeMaxDynamicSharedMemorySize, ATT_SMEM);

    const int M = BB * TT;  // 4096

    // 0) convert operands to fp16
    split1_kernel<<<8192, 256>>>(hidden, hid, (BB * TT * HIDD) / 4);
    split1_kernel<<<8192, 256>>>(w_qkv, wqkv, (QKVW * HIDD) / 4);
    split1_kernel<<<4096, 256>>>(w_o, wo, (HIDD * HIDD) / 4);

    // 1) QKV projection -> g_qkv fp32
    gemm_pre_kernel<<<dim3(QKVW / 128, M / 128), 256, GT_SMEM>>>(
        hid, wqkv, qkv_f, M, QKVW, HIDD);

    // 2) RoPE + scale-fold + fp16 convert -> g_qkvb
    ropesplit_kernel<<<dim3(BB * TT, 8), 128>>>(fcos, fsin);

    // 3) causal GQA attention (tensor cores) -> g_attnb fp16
    attn_kernel<<<dim3(TT / 64, NH, BB), 128, ATT_SMEM>>>();

    // 4) output projection -> d_out fp32
    gemm_pre_kernel<<<dim3(HIDD / 128, M / 128), 256, GT_SMEM>>>(
        attnb, wo, out, M, HIDD, HIDD);
}

// round 9
// speedup vs baseline: 2.5042x; 1.1036x over previous
#include <cuda_runtime.h>
#include <cuda_fp16.h>
#include <math.h>
#include <stdint.h>

// Problem constants
#define BB 2
#define TT 2048
#define HIDD 2048
#define NH 16
#define NKV 8
#define HD 128
#define QKVW 4096   // (NH + 2*NKV) * HD
#define KOFF 2048   // NH*HD
#define VOFF 3072   // NH*HD + NKV*HD
#define ATT_SCALE 0.08838834764831845f  // 128^-0.5

// Scratch (allocation-free rule: __device__ globals)
__device__ __half g_hid[(size_t)BB * TT * HIDD];          // activations fp16
__device__ __half g_wqkv[(size_t)QKVW * HIDD];            // Q-rows pre-scaled
__device__ __half g_wo[(size_t)HIDD * HIDD];
__device__ __half g_qkvb[(size_t)BB * TT * QKVW];         // qkv fp16 (roped in-place)
__device__ __half g_attnb[(size_t)BB * TT * HIDD];        // attn out fp16

// ---------------------------------------------------------------------------
// Helpers (arch-stable PTX: cp.async + ldmatrix + mma.sync, sm_80 level)
// ---------------------------------------------------------------------------
__device__ __forceinline__ uint32_t smem_u32(const void* p) {
    uint32_t a;
    asm("{ .reg .u64 t; cvta.to.shared.u64 t, %1; cvt.u32.u64 %0, t; }"
        : "=r"(a) : "l"(p));
    return a;
}

// pack two f32 -> f16x2 (lo half = x, hi half = y)
__device__ __forceinline__ uint32_t pack_hf2(float x, float y) {
    __half2 h = __floats2half2_rn(x, y);
    return *reinterpret_cast<uint32_t*>(&h);
}

#define LDM_X4(r, a)                                                            \
    asm volatile("ldmatrix.sync.aligned.m8n8.x4.shared.b16 {%0,%1,%2,%3}, [%4];"\
        : "=r"((r)[0]), "=r"((r)[1]), "=r"((r)[2]), "=r"((r)[3]) : "r"(a))

#define LDM_X4T(r, a)                                                           \
    asm volatile("ldmatrix.sync.aligned.m8n8.x4.trans.shared.b16 "              \
                 "{%0,%1,%2,%3}, [%4];"                                         \
        : "=r"((r)[0]), "=r"((r)[1]), "=r"((r)[2]), "=r"((r)[3]) : "r"(a))

__device__ __forceinline__ void mma_f16(float* d, const uint32_t* a, const uint32_t* b) {
    asm volatile(
        "mma.sync.aligned.m16n8k16.row.col.f32.f16.f16.f32 "
        "{%0,%1,%2,%3}, {%4,%5,%6,%7}, {%8,%9}, {%0,%1,%2,%3};"
        : "+f"(d[0]), "+f"(d[1]), "+f"(d[2]), "+f"(d[3])
        : "r"(a[0]), "r"(a[1]), "r"(a[2]), "r"(a[3]), "r"(b[0]), "r"(b[1]));
}

#define CP_A16(dst, src)                                                        \
    asm volatile("cp.async.cg.shared.global [%0], [%1], 16;"                    \
        :: "r"(dst), "l"(src))
#define CP_COMMIT() asm volatile("cp.async.commit_group;" ::: "memory")
#define CP_WAIT(n)  asm volatile("cp.async.wait_group %0;" :: "n"(n) : "memory")

// ---------------------------------------------------------------------------
// fp32 -> fp16 (round-to-nearest), optional scaling of the first scale_n4
// float4-chunks (used to fold ATT_SCALE into the Q rows of w_qkv).
// ---------------------------------------------------------------------------
__global__ void split1_kernel(const float* __restrict__ src,
                              __half* __restrict__ dst, int n4, int scale_n4)
{
    int i = blockIdx.x * blockDim.x + threadIdx.x;
    if (i >= n4) return;
    float sc = (i < scale_n4) ? ATT_SCALE : 1.f;
    float4 v = ((const float4*)src)[i];
    ((uint2*)dst)[i] = make_uint2(pack_hf2(v.x * sc, v.y * sc),
                                  pack_hf2(v.z * sc, v.w * sc));
}

// ---------------------------------------------------------------------------
// RoPE in-place on fp16 g_qkvb, Q+K heads only (head 0..23).
// grid (B*T, 3) x 256 threads; thread = (head, dpair).
// ---------------------------------------------------------------------------
__global__ void rope16_kernel(const float* __restrict__ cosT,
                              const float* __restrict__ sinT)
{
    const int bt = blockIdx.x;
    const int t  = bt & (TT - 1);
    const int slot = blockIdx.y * blockDim.x + threadIdx.x;   // 0..767
    const int head = slot >> 5;                               // 0..23
    const int dp   = (slot & 31) << 1;                        // 0,2,..,62
    __half* row = g_qkvb + (size_t)bt * QKVW + head * HD;

    uint32_t u1 = *(uint32_t*)(row + dp);
    uint32_t u2 = *(uint32_t*)(row + dp + 64);
    float2 x1 = __half22float2(*(__half2*)&u1);
    float2 x2 = __half22float2(*(__half2*)&u2);
    float2 c = *(const float2*)(cosT + t * 64 + dp);
    float2 s = *(const float2*)(sinT + t * 64 + dp);
    *(uint32_t*)(row + dp)      = pack_hf2(x1.x * c.x - x2.x * s.x,
                                           x1.y * c.y - x2.y * s.y);
    *(uint32_t*)(row + dp + 64) = pack_hf2(x1.x * s.x + x2.x * c.x,
                                           x1.y * s.y + x2.y * c.y);
}

// ---------------------------------------------------------------------------
// Tensor-core NT GEMM, single fp16: C[M,N] = A[M,K] @ B[N,K]^T, fp32 accum.
// CTA 128x128, BK=32, 8 warps (4m x 2n -> 32x64 warp tile).
// 3-stage cp.async ring, ONE barrier per chunk, 2 CTAs/SM.
// SMEM rows: 32 fp16 + 8 pad = 80 B (conflict-free ldmatrix).
// Output fp16 (F16=1) or fp32 (F16=0).
// ---------------------------------------------------------------------------
#define GT_BUF  10240                // one 128x32 fp16 tile (rows of 80 B)
#define GT_STG  (2 * GT_BUF)         // A, B = 20480
#define GT_SMEM (3 * GT_STG)         // 3 stages = 61440

#define GT_ISSUE(c)                                                            \
    do {                                                                       \
        uint32_t sb_ = smb + ((c) % 3) * GT_STG;                               \
        _Pragma("unroll")                                                      \
        for (int i_ = 0; i_ < 4; i_++) {   /* 2 bufs x 512 chunks / 256 thr */ \
            const int bu_ = i_ >> 1;                                           \
            int w_ = (i_ & 1) * 256 + tid;                                     \
            int r_ = w_ >> 2, ch_ = w_ & 3;                                    \
            CP_A16(sb_ + bu_ * GT_BUF + r_ * 80 + ch_ * 16,                    \
                   tb[bu_] + (size_t)r_ * K + (c) * 32 + ch_ * 8);             \
        }                                                                      \
    } while (0)

template <int F16>
__global__ void __launch_bounds__(256, 2) gemm_pre_kernel(
    const __half* __restrict__ A, const __half* __restrict__ B,
    void* __restrict__ Cv, int M, int N, int K)
{
    extern __shared__ char sm[];
    const uint32_t smb = smem_u32(sm);
    const int tid = threadIdx.x;
    const int wid = tid >> 5, lane = tid & 31;
    const int m0 = blockIdx.y * 128, n0 = blockIdx.x * 128;
    const int wm = wid & 3, wn = wid >> 2;          // 4m x 2n, 32x64 each
    const int quad = lane >> 3, rin = lane & 7;

    const __half* tb[2] = { A + (size_t)m0 * K, B + (size_t)n0 * K };
    const int NC = K / 32;

    float acc[2][8][4];
#pragma unroll
    for (int i = 0; i < 2; i++)
#pragma unroll
        for (int j = 0; j < 8; j++)
#pragma unroll
            for (int u = 0; u < 4; u++) acc[i][j][u] = 0.f;

    GT_ISSUE(0); CP_COMMIT();
    GT_ISSUE(1); CP_COMMIT();

    for (int c = 0; c < NC; c++) {
        CP_WAIT(1);
        __syncthreads();   // group c visible to all; stage (c+2)%3 free (read in c-1)

        const uint32_t aBase = smb + (c % 3) * GT_STG;
        const uint32_t bBase = aBase + GT_BUF;
#pragma unroll
        for (int ks = 0; ks < 2; ks++) {
            const int k0 = ks * 16;
            uint32_t af[2][4];
#pragma unroll
            for (int mt = 0; mt < 2; mt++) {
                int row = wm * 32 + mt * 16 + (quad & 1) * 8 + rin;
                int col = k0 + (quad >> 1) * 8;
                LDM_X4(af[mt], aBase + row * 80 + col * 2);
            }
#pragma unroll
            for (int nb = 0; nb < 4; nb++) {
                uint32_t b4[4];
                int rowb = wn * 64 + nb * 16 + (quad >> 1) * 8 + rin;
                int colb = k0 + (quad & 1) * 8;
                LDM_X4(b4, bBase + rowb * 80 + colb * 2);
#pragma unroll
                for (int mt = 0; mt < 2; mt++)
#pragma unroll
                    for (int hf = 0; hf < 2; hf++)
                        mma_f16(acc[mt][nb * 2 + hf], af[mt], &b4[hf * 2]);
            }
        }

        if (c + 2 < NC) { GT_ISSUE(c + 2); CP_COMMIT(); }
    }

    const int lr = lane >> 2;
    const int lc = (lane & 3) * 2;
#pragma unroll
    for (int mt = 0; mt < 2; mt++)
#pragma unroll
        for (int nt = 0; nt < 8; nt++) {
            int row = m0 + wm * 32 + mt * 16 + lr;
            int col = n0 + wn * 64 + nt * 8 + lc;
            if (F16) {
                __half* C = (__half*)Cv;
                *(uint32_t*)(C + (size_t)row * N + col) =
                    pack_hf2(acc[mt][nt][0], acc[mt][nt][1]);
                *(uint32_t*)(C + (size_t)(row + 8) * N + col) =
                    pack_hf2(acc[mt][nt][2], acc[mt][nt][3]);
            } else {
                float* C = (float*)Cv;
                *(float2*)(C + (size_t)row * N + col) =
                    make_float2(acc[mt][nt][0], acc[mt][nt][1]);
                *(float2*)(C + (size_t)(row + 8) * N + col) =
                    make_float2(acc[mt][nt][2], acc[mt][nt][3]);
            }
        }
}

// ---------------------------------------------------------------------------
// Tensor-core causal GQA flash attention (single fp16, fp32 accum).
// S = Q @ K^T; O += P @ V. CTA: 64 Q rows x (head, batch); 4 warps.
// SMEM tiles (64 rows x 272 B): Q, K, V.
// ---------------------------------------------------------------------------
#define AQLD  272
#define ATILE 17408                 // 64 rows x 272 B
#define ATT_SMEM (3 * ATILE)        // 52224 B

__global__ void __launch_bounds__(128, 3) attn_kernel()
{
    extern __shared__ char sm[];
    const uint32_t smb = smem_u32(sm);
    const int tid = threadIdx.x;
    const int wid = tid >> 5, lane = tid & 31;
    const int q0 = blockIdx.x * 64;
    const int h = blockIdx.y, b = blockIdx.z;
    const int khh = h >> 1;                 // GQA: n_rep = 2

    const int l8  = (lane >> 3) & 1;
    const int l16 = lane >> 4;
    const int rin = lane & 7;

    // ---- load Q tile once (cp.async) ----
    {
        const __half* qh = g_qkvb + ((size_t)(b * TT + q0)) * QKVW + h * HD;
#pragma unroll
        for (int i = 0; i < 8; i++) {
            int w = i * 128 + tid;
            int r = w >> 4, ch = w & 15;
            CP_A16(smb + r * AQLD + ch * 16, qh + (size_t)r * QKVW + ch * 8);
        }
        CP_COMMIT();
    }

    float o[16][4];
#pragma unroll
    for (int i = 0; i < 16; i++)
#pragma unroll
        for (int u = 0; u < 4; u++) o[i][u] = 0.f;
    float m0r = -1e30f, m1r = -1e30f, l0 = 0.f, l1 = 0.f;

    const size_t bbase = (size_t)(b * TT);
    const int ntiles = (q0 >> 6) + 1;

    for (int jt = 0; jt < ntiles; jt++) {
        const int kb = jt << 6;
        __syncthreads();   // everyone done reading previous K/V tiles

        // ---- load K,V tiles ----
        {
            const size_t rb = (bbase + kb) * QKVW;
            const __half* s0 = g_qkvb + rb + KOFF + khh * HD;
            const __half* s1 = g_qkvb + rb + VOFF + khh * HD;
#pragma unroll
            for (int i = 0; i < 16; i++) {
                const int t = i >> 3;
                int w = (i & 7) * 128 + tid;
                int r = w >> 4, ch = w & 15;
                const __half* src = (t ? s1 : s0) + (size_t)r * QKVW + ch * 8;
                CP_A16(smb + (1 + t) * ATILE + r * AQLD + ch * 16, src);
            }
            CP_COMMIT();
        }
        CP_WAIT(0);
        __syncthreads();

        // ---- S = Q @ K^T  (Q pre-scaled by ATT_SCALE via w_qkv) ----
        float s[8][4];
#pragma unroll
        for (int i = 0; i < 8; i++)
#pragma unroll
            for (int u = 0; u < 4; u++) s[i][u] = 0.f;

#pragma unroll
        for (int ks = 0; ks < 8; ks++) {
            const int k0 = ks * 16;
            uint32_t aq[4];
            LDM_X4(aq, smb + (wid * 16 + l8 * 8 + rin) * AQLD + (k0 + l16 * 8) * 2);
#pragma unroll
            for (int nb = 0; nb < 4; nb++) {
                uint32_t k4[4];
                LDM_X4(k4, smb + ATILE + (nb * 16 + l16 * 8 + rin) * AQLD
                           + (k0 + l8 * 8) * 2);
#pragma unroll
                for (int hf = 0; hf < 2; hf++)
                    mma_f16(s[nb * 2 + hf], aq, &k4[hf * 2]);
            }
        }

        // ---- causal mask on the diagonal tile ----
        if (kb == q0) {
            const int r0l = wid * 16 + (lane >> 2);
#pragma unroll
            for (int nt = 0; nt < 8; nt++) {
                int c0 = nt * 8 + 2 * (lane & 3);
                if (c0     > r0l)     s[nt][0] = -1e30f;
                if (c0 + 1 > r0l)     s[nt][1] = -1e30f;
                if (c0     > r0l + 8) s[nt][2] = -1e30f;
                if (c0 + 1 > r0l + 8) s[nt][3] = -1e30f;
            }
        }

        // ---- register online softmax (rows lr and lr+8) ----
        float tm0 = -1e30f, tm1 = -1e30f;
#pragma unroll
        for (int nt = 0; nt < 8; nt++) {
            tm0 = fmaxf(tm0, fmaxf(s[nt][0], s[nt][1]));
            tm1 = fmaxf(tm1, fmaxf(s[nt][2], s[nt][3]));
        }
        tm0 = fmaxf(tm0, __shfl_xor_sync(0xffffffffu, tm0, 1));
        tm0 = fmaxf(tm0, __shfl_xor_sync(0xffffffffu, tm0, 2));
        tm1 = fmaxf(tm1, __shfl_xor_sync(0xffffffffu, tm1, 1));
        tm1 = fmaxf(tm1, __shfl_xor_sync(0xffffffffu, tm1, 2));
        float nm0 = fmaxf(m0r, tm0), nm1 = fmaxf(m1r, tm1);
        float cor0 = __expf(m0r - nm0), cor1 = __expf(m1r - nm1);
        m0r = nm0; m1r = nm1;

        float sum0 = 0.f, sum1 = 0.f;
#pragma unroll
        for (int nt = 0; nt < 8; nt++) {
            s[nt][0] = __expf(s[nt][0] - nm0);
            s[nt][1] = __expf(s[nt][1] - nm0);
            s[nt][2] = __expf(s[nt][2] - nm1);
            s[nt][3] = __expf(s[nt][3] - nm1);
            sum0 += s[nt][0] + s[nt][1];
            sum1 += s[nt][2] + s[nt][3];
        }
        sum0 += __shfl_xor_sync(0xffffffffu, sum0, 1);
        sum0 += __shfl_xor_sync(0xffffffffu, sum0, 2);
        sum1 += __shfl_xor_sync(0xffffffffu, sum1, 1);
        sum1 += __shfl_xor_sync(0xffffffffu, sum1, 2);
        l0 = l0 * cor0 + sum0;
        l1 = l1 * cor1 + sum1;

#pragma unroll
        for (int nt = 0; nt < 16; nt++) {
            o[nt][0] *= cor0; o[nt][1] *= cor0;
            o[nt][2] *= cor1; o[nt][3] *= cor1;
        }

        // ---- O += P @ V : P frags built in-register (fp16) ----
#pragma unroll
        for (int kk = 0; kk < 4; kk++) {
            uint32_t ah[4];
            ah[0] = pack_hf2(s[2 * kk][0],     s[2 * kk][1]);
            ah[1] = pack_hf2(s[2 * kk][2],     s[2 * kk][3]);
            ah[2] = pack_hf2(s[2 * kk + 1][0], s[2 * kk + 1][1]);
            ah[3] = pack_hf2(s[2 * kk + 1][2], s[2 * kk + 1][3]);
#pragma unroll
            for (int nb = 0; nb < 8; nb++) {
                uint32_t v4[4];
                LDM_X4T(v4, smb + 2 * ATILE + (kk * 16 + l8 * 8 + rin) * AQLD
                            + (nb * 16 + l16 * 8) * 2);
#pragma unroll
                for (int hf = 0; hf < 2; hf++)
                    mma_f16(o[nb * 2 + hf], ah, &v4[hf * 2]);
            }
        }
    }

    // ---- epilogue: normalize + fp16 store for the O-projection ----
    float inv0 = 1.f / l0, inv1 = 1.f / l1;
    const size_t r0 = bbase + q0 + wid * 16 + (lane >> 2);
    const int gc = h * HD + 2 * (lane & 3);
#pragma unroll
    for (int nt = 0; nt < 16; nt++) {
        int col = gc + nt * 8;
        *(uint32_t*)(g_attnb + r0 * HIDD + col) =
            pack_hf2(o[nt][0] * inv0, o[nt][1] * inv0);
        *(uint32_t*)(g_attnb + (r0 + 8) * HIDD + col) =
            pack_hf2(o[nt][2] * inv1, o[nt][3] * inv1);
    }
}

// ---------------------------------------------------------------------------
extern "C" void kernel_launch(void* const* d_in, const int* in_sizes, int n_in,
                              void* d_out, int out_size)
{
    const float* hidden = (const float*)d_in[0];
    const float* fcos   = (const float*)d_in[1];
    const float* fsin   = (const float*)d_in[2];
    const float* w_qkv  = (const float*)d_in[6];
    const float* w_o    = (const float*)d_in[7];
    float* out = (float*)d_out;

    __half *hid, *wqkv, *wo, *qkvb, *attnb;
    cudaGetSymbolAddress((void**)&hid,   g_hid);
    cudaGetSymbolAddress((void**)&wqkv,  g_wqkv);
    cudaGetSymbolAddress((void**)&wo,    g_wo);
    cudaGetSymbolAddress((void**)&qkvb,  g_qkvb);
    cudaGetSymbolAddress((void**)&attnb, g_attnb);

    cudaFuncSetAttribute(gemm_pre_kernel<1>,
                         cudaFuncAttributeMaxDynamicSharedMemorySize, GT_SMEM);
    cudaFuncSetAttribute(gemm_pre_kernel<0>,
                         cudaFuncAttributeMaxDynamicSharedMemorySize, GT_SMEM);
    cudaFuncSetAttribute(attn_kernel,
                         cudaFuncAttributeMaxDynamicSharedMemorySize, ATT_SMEM);

    const int M = BB * TT;  // 4096

    // 0) convert operands to fp16 (ATT_SCALE folded into Q rows of w_qkv)
    split1_kernel<<<8192, 256>>>(hidden, hid, (BB * TT * HIDD) / 4, 0);
    split1_kernel<<<8192, 256>>>(w_qkv, wqkv, (QKVW * HIDD) / 4,
                                 (KOFF * HIDD) / 4);
    split1_kernel<<<4096, 256>>>(w_o, wo, (HIDD * HIDD) / 4, 0);

    // 1) QKV projection -> g_qkvb fp16 (direct)
    gemm_pre_kernel<1><<<dim3(QKVW / 128, M / 128), 256, GT_SMEM>>>(
        hid, wqkv, qkvb, M, QKVW, HIDD);

    // 2) RoPE in-place on Q,K heads of g_qkvb
    rope16_kernel<<<dim3(BB * TT, 3), 256>>>(fcos, fsin);

    // 3) causal GQA attention (tensor cores) -> g_attnb fp16
    attn_kernel<<<dim3(TT / 64, NH, BB), 128, ATT_SMEM>>>();

    // 4) output projection -> d_out fp32
    gemm_pre_kernel<0><<<dim3(HIDD / 128, M / 128), 256, GT_SMEM>>>(
        attnb, wo, out, M, HIDD, HIDD);
}

// round 10
// speedup vs baseline: 2.6885x; 1.0736x over previous
#include <cuda_runtime.h>
#include <cuda_fp16.h>
#include <math.h>
#include <stdint.h>

// Problem constants
#define BB 2
#define TT 2048
#define HIDD 2048
#define NH 16
#define NKV 8
#define HD 128
#define QKVW 4096   // (NH + 2*NKV) * HD
#define KOFF 2048   // NH*HD
#define VOFF 3072   // NH*HD + NKV*HD
#define ATT_SCALE 0.08838834764831845f  // 128^-0.5

// Scratch (allocation-free rule: __device__ globals)
__device__ __half g_hid[(size_t)BB * TT * HIDD];          // activations fp16
__device__ __half g_wqkv[(size_t)QKVW * HIDD];            // Q-rows pre-scaled
__device__ __half g_wo[(size_t)HIDD * HIDD];
__device__ __half g_qkvb[(size_t)BB * TT * QKVW];         // qkv fp16 (roped in-place)
__device__ __half g_attnb[(size_t)BB * TT * HIDD];        // attn out fp16

// ---------------------------------------------------------------------------
// Helpers (arch-stable PTX: cp.async + ldmatrix + mma.sync, sm_80 level)
// ---------------------------------------------------------------------------
__device__ __forceinline__ uint32_t smem_u32(const void* p) {
    uint32_t a;
    asm("{ .reg .u64 t; cvta.to.shared.u64 t, %1; cvt.u32.u64 %0, t; }"
        : "=r"(a) : "l"(p));
    return a;
}

// pack two f32 -> f16x2 (lo half = x, hi half = y)
__device__ __forceinline__ uint32_t pack_hf2(float x, float y) {
    __half2 h = __floats2half2_rn(x, y);
    return *reinterpret_cast<uint32_t*>(&h);
}

#define LDM_X4(r, a)                                                            \
    asm volatile("ldmatrix.sync.aligned.m8n8.x4.shared.b16 {%0,%1,%2,%3}, [%4];"\
        : "=r"((r)[0]), "=r"((r)[1]), "=r"((r)[2]), "=r"((r)[3]) : "r"(a))

#define LDM_X4T(r, a)                                                           \
    asm volatile("ldmatrix.sync.aligned.m8n8.x4.trans.shared.b16 "              \
                 "{%0,%1,%2,%3}, [%4];"                                         \
        : "=r"((r)[0]), "=r"((r)[1]), "=r"((r)[2]), "=r"((r)[3]) : "r"(a))

__device__ __forceinline__ void mma_f16(float* d, const uint32_t* a, const uint32_t* b) {
    asm volatile(
        "mma.sync.aligned.m16n8k16.row.col.f32.f16.f16.f32 "
        "{%0,%1,%2,%3}, {%4,%5,%6,%7}, {%8,%9}, {%0,%1,%2,%3};"
        : "+f"(d[0]), "+f"(d[1]), "+f"(d[2]), "+f"(d[3])
        : "r"(a[0]), "r"(a[1]), "r"(a[2]), "r"(a[3]), "r"(b[0]), "r"(b[1]));
}

#define CP_A16(dst, src)                                                        \
    asm volatile("cp.async.cg.shared.global [%0], [%1], 16;"                    \
        :: "r"(dst), "l"(src))
#define CP_COMMIT() asm volatile("cp.async.commit_group;" ::: "memory")
#define CP_WAIT(n)  asm volatile("cp.async.wait_group %0;" :: "n"(n) : "memory")

// ---------------------------------------------------------------------------
// Fused fp32 -> fp16 convert of hidden, w_qkv (Q rows pre-scaled), w_o.
// One grid over all three tensors (float4-chunk granularity).
// ---------------------------------------------------------------------------
#define N4_HID  ((BB * TT * HIDD) / 4)     // 2M
#define N4_WQKV ((QKVW * HIDD) / 4)        // 2M
#define N4_WQ   ((KOFF * HIDD) / 4)        // Q rows of w_qkv
#define N4_WO   ((HIDD * HIDD) / 4)        // 1M
__global__ void convert_all_kernel(const float* __restrict__ hidden,
                                   const float* __restrict__ w_qkv,
                                   const float* __restrict__ w_o)
{
    int i = blockIdx.x * blockDim.x + threadIdx.x;
    const float* src;
    __half* dst;
    float sc = 1.f;
    int j = i;
    if (j < N4_HID) {
        src = hidden; dst = g_hid;
    } else if ((j -= N4_HID) < N4_WQKV) {
        src = w_qkv; dst = g_wqkv;
        if (j < N4_WQ) sc = ATT_SCALE;
    } else if ((j -= N4_WQKV) < N4_WO) {
        src = w_o; dst = g_wo;
    } else return;
    float4 v = ((const float4*)src)[j];
    ((uint2*)dst)[j] = make_uint2(pack_hf2(v.x * sc, v.y * sc),
                                  pack_hf2(v.z * sc, v.w * sc));
}

// ---------------------------------------------------------------------------
// RoPE in-place on fp16 g_qkvb, Q+K heads only (head 0..23).
// ---------------------------------------------------------------------------
__global__ void rope16_kernel(const float* __restrict__ cosT,
                              const float* __restrict__ sinT)
{
    const int bt = blockIdx.x;
    const int t  = bt & (TT - 1);
    const int slot = blockIdx.y * blockDim.x + threadIdx.x;   // 0..767
    const int head = slot >> 5;                               // 0..23
    const int dp   = (slot & 31) << 1;                        // 0,2,..,62
    __half* row = g_qkvb + (size_t)bt * QKVW + head * HD;

    uint32_t u1 = *(uint32_t*)(row + dp);
    uint32_t u2 = *(uint32_t*)(row + dp + 64);
    float2 x1 = __half22float2(*(__half2*)&u1);
    float2 x2 = __half22float2(*(__half2*)&u2);
    float2 c = *(const float2*)(cosT + t * 64 + dp);
    float2 s = *(const float2*)(sinT + t * 64 + dp);
    *(uint32_t*)(row + dp)      = pack_hf2(x1.x * c.x - x2.x * s.x,
                                           x1.y * c.y - x2.y * s.y);
    *(uint32_t*)(row + dp + 64) = pack_hf2(x1.x * s.x + x2.x * c.x,
                                           x1.y * s.y + x2.y * c.y);
}

// ---------------------------------------------------------------------------
// Tensor-core NT GEMM, single fp16: C[M,N] = A[M,K] @ B[N,K]^T, fp32 accum.
// CTA 128x128, BK=64 (half the barriers of BK=32), 8 warps (4m x 2n).
// 3-stage cp.async ring, ONE barrier per chunk, 2 CTAs/SM.
// SMEM rows: 64 fp16 + 8 pad = 144 B (rows advance 4 banks -> conflict-free).
// Output fp16 (F16=1) or fp32 (F16=0).
// ---------------------------------------------------------------------------
#define GT_ROWB 144
#define GT_BUF  (128 * GT_ROWB)      // 18432 per 128x64 fp16 tile
#define GT_STG  (2 * GT_BUF)         // A, B = 36864
#define GT_SMEM (3 * GT_STG)         // 3 stages = 110592

#define GT_ISSUE(c)                                                            \
    do {                                                                       \
        uint32_t sb_ = smb + ((c) % 3) * GT_STG;                               \
        _Pragma("unroll")                                                      \
        for (int i_ = 0; i_ < 8; i_++) {  /* 2 bufs x 1024 chunks / 256 thr */ \
            const int bu_ = i_ >> 2;                                           \
            int w_ = (i_ & 3) * 256 + tid;                                     \
            int r_ = w_ >> 3, ch_ = w_ & 7;                                    \
            CP_A16(sb_ + bu_ * GT_BUF + r_ * GT_ROWB + ch_ * 16,               \
                   tb[bu_] + (size_t)r_ * K + (c) * 64 + ch_ * 8);             \
        }                                                                      \
    } while (0)

template <int F16>
__global__ void __launch_bounds__(256, 2) gemm_pre_kernel(
    const __half* __restrict__ A, const __half* __restrict__ B,
    void* __restrict__ Cv, int M, int N, int K)
{
    extern __shared__ char sm[];
    const uint32_t smb = smem_u32(sm);
    const int tid = threadIdx.x;
    const int wid = tid >> 5, lane = tid & 31;
    const int m0 = blockIdx.y * 128, n0 = blockIdx.x * 128;
    const int wm = wid & 3, wn = wid >> 2;          // 4m x 2n, 32x64 each
    const int quad = lane >> 3, rin = lane & 7;

    const __half* tb[2] = { A + (size_t)m0 * K, B + (size_t)n0 * K };
    const int NC = K / 64;

    float acc[2][8][4];
#pragma unroll
    for (int i = 0; i < 2; i++)
#pragma unroll
        for (int j = 0; j < 8; j++)
#pragma unroll
            for (int u = 0; u < 4; u++) acc[i][j][u] = 0.f;

    GT_ISSUE(0); CP_COMMIT();
    GT_ISSUE(1); CP_COMMIT();

    for (int c = 0; c < NC; c++) {
        CP_WAIT(1);
        __syncthreads();   // group c visible; stage (c+2)%3 free (read in c-1)

        const uint32_t aBase = smb + (c % 3) * GT_STG;
        const uint32_t bBase = aBase + GT_BUF;
#pragma unroll
        for (int ks = 0; ks < 4; ks++) {
            const int k0 = ks * 16;
            uint32_t af[2][4];
#pragma unroll
            for (int mt = 0; mt < 2; mt++) {
                int row = wm * 32 + mt * 16 + (quad & 1) * 8 + rin;
                int col = k0 + (quad >> 1) * 8;
                LDM_X4(af[mt], aBase + row * GT_ROWB + col * 2);
            }
#pragma unroll
            for (int nb = 0; nb < 4; nb++) {
                uint32_t b4[4];
                int rowb = wn * 64 + nb * 16 + (quad >> 1) * 8 + rin;
                int colb = k0 + (quad & 1) * 8;
                LDM_X4(b4, bBase + rowb * GT_ROWB + colb * 2);
#pragma unroll
                for (int mt = 0; mt < 2; mt++)
#pragma unroll
                    for (int hf = 0; hf < 2; hf++)
                        mma_f16(acc[mt][nb * 2 + hf], af[mt], &b4[hf * 2]);
            }
        }

        if (c + 2 < NC) { GT_ISSUE(c + 2); CP_COMMIT(); }
    }

    const int lr = lane >> 2;
    const int lc = (lane & 3) * 2;
#pragma unroll
    for (int mt = 0; mt < 2; mt++)
#pragma unroll
        for (int nt = 0; nt < 8; nt++) {
            int row = m0 + wm * 32 + mt * 16 + lr;
            int col = n0 + wn * 64 + nt * 8 + lc;
            if (F16) {
                __half* C = (__half*)Cv;
                *(uint32_t*)(C + (size_t)row * N + col) =
                    pack_hf2(acc[mt][nt][0], acc[mt][nt][1]);
                *(uint32_t*)(C + (size_t)(row + 8) * N + col) =
                    pack_hf2(acc[mt][nt][2], acc[mt][nt][3]);
            } else {
                float* C = (float*)Cv;
                *(float2*)(C + (size_t)row * N + col) =
                    make_float2(acc[mt][nt][0], acc[mt][nt][1]);
                *(float2*)(C + (size_t)(row + 8) * N + col) =
                    make_float2(acc[mt][nt][2], acc[mt][nt][3]);
            }
        }
}

// ---------------------------------------------------------------------------
// Tensor-core causal GQA flash attention (single fp16, fp32 accum).
// Double-buffered K/V: load of tile jt+1 overlaps compute on tile jt.
// SMEM: Q + 2x(K,V) = 5 tiles (64 rows x 272 B each).
// ---------------------------------------------------------------------------
#define AQLD  272
#define ATILE 17408                 // 64 rows x 272 B
#define ATT_SMEM (5 * ATILE)        // 87040 B

__global__ void __launch_bounds__(128, 2) attn_kernel()
{
    extern __shared__ char sm[];
    const uint32_t smb = smem_u32(sm);
    const int tid = threadIdx.x;
    const int wid = tid >> 5, lane = tid & 31;
    const int q0 = blockIdx.x * 64;
    const int h = blockIdx.y, b = blockIdx.z;
    const int khh = h >> 1;                 // GQA: n_rep = 2

    const int l8  = (lane >> 3) & 1;
    const int l16 = lane >> 4;
    const int rin = lane & 7;

    const size_t bbase = (size_t)(b * TT);
    const int ntiles = (q0 >> 6) + 1;

    // KV buffer b: K tile at ATILE*(1+2b), V tile at ATILE*(2+2b)
#define ATT_LOAD_KV(tileidx, bufsel)                                           \
    do {                                                                       \
        const size_t rb_ = (bbase + (size_t)(tileidx) * 64) * QKVW;            \
        const __half* s0_ = g_qkvb + rb_ + KOFF + khh * HD;                    \
        const __half* s1_ = g_qkvb + rb_ + VOFF + khh * HD;                    \
        uint32_t kb_ = smb + (1 + 2 * (bufsel)) * ATILE;                       \
        _Pragma("unroll")                                                      \
        for (int i_ = 0; i_ < 16; i_++) {                                      \
            const int t_ = i_ >> 3;                                            \
            int w_ = (i_ & 7) * 128 + tid;                                     \
            int r_ = w_ >> 4, ch_ = w_ & 15;                                   \
            const __half* src_ = (t_ ? s1_ : s0_) + (size_t)r_ * QKVW + ch_ * 8;\
            CP_A16(kb_ + t_ * ATILE + r_ * AQLD + ch_ * 16, src_);             \
        }                                                                      \
    } while (0)

    // ---- prologue: Q tile (group), then KV tile 0 (group) ----
    {
        const __half* qh = g_qkvb + (bbase + q0) * QKVW + h * HD;
#pragma unroll
        for (int i = 0; i < 8; i++) {
            int w = i * 128 + tid;
            int r = w >> 4, ch = w & 15;
            CP_A16(smb + r * AQLD + ch * 16, qh + (size_t)r * QKVW + ch * 8);
        }
        CP_COMMIT();
    }
    ATT_LOAD_KV(0, 0);
    CP_COMMIT();

    float o[16][4];
#pragma unroll
    for (int i = 0; i < 16; i++)
#pragma unroll
        for (int u = 0; u < 4; u++) o[i][u] = 0.f;
    float m0r = -1e30f, m1r = -1e30f, l0 = 0.f, l1 = 0.f;

    for (int jt = 0; jt < ntiles; jt++) {
        __syncthreads();   // all warps done reading buf (jt+1)&1 (iter jt-1)
        if (jt + 1 < ntiles) ATT_LOAD_KV(jt + 1, (jt + 1) & 1);
        CP_COMMIT();       // (possibly empty) group keeps numbering consistent
        CP_WAIT(1);        // group for tile jt complete
        __syncthreads();

        const uint32_t kBase = smb + (1 + 2 * (jt & 1)) * ATILE;
        const uint32_t vBase = kBase + ATILE;
        const int kb = jt << 6;

        // ---- S = Q @ K^T  (Q pre-scaled by ATT_SCALE via w_qkv) ----
        float s[8][4];
#pragma unroll
        for (int i = 0; i < 8; i++)
#pragma unroll
            for (int u = 0; u < 4; u++) s[i][u] = 0.f;

#pragma unroll
        for (int ks = 0; ks < 8; ks++) {
            const int k0 = ks * 16;
            uint32_t aq[4];
            LDM_X4(aq, smb + (wid * 16 + l8 * 8 + rin) * AQLD + (k0 + l16 * 8) * 2);
#pragma unroll
            for (int nb = 0; nb < 4; nb++) {
                uint32_t k4[4];
                LDM_X4(k4, kBase + (nb * 16 + l16 * 8 + rin) * AQLD
                           + (k0 + l8 * 8) * 2);
#pragma unroll
                for (int hf = 0; hf < 2; hf++)
                    mma_f16(s[nb * 2 + hf], aq, &k4[hf * 2]);
            }
        }

        // ---- causal mask on the diagonal tile ----
        if (kb == q0) {
            const int r0l = wid * 16 + (lane >> 2);
#pragma unroll
            for (int nt = 0; nt < 8; nt++) {
                int c0 = nt * 8 + 2 * (lane & 3);
                if (c0     > r0l)     s[nt][0] = -1e30f;
                if (c0 + 1 > r0l)     s[nt][1] = -1e30f;
                if (c0     > r0l + 8) s[nt][2] = -1e30f;
                if (c0 + 1 > r0l + 8) s[nt][3] = -1e30f;
            }
        }

        // ---- register online softmax (rows lr and lr+8) ----
        float tm0 = -1e30f, tm1 = -1e30f;
#pragma unroll
        for (int nt = 0; nt < 8; nt++) {
            tm0 = fmaxf(tm0, fmaxf(s[nt][0], s[nt][1]));
            tm1 = fmaxf(tm1, fmaxf(s[nt][2], s[nt][3]));
        }
        tm0 = fmaxf(tm0, __shfl_xor_sync(0xffffffffu, tm0, 1));
        tm0 = fmaxf(tm0, __shfl_xor_sync(0xffffffffu, tm0, 2));
        tm1 = fmaxf(tm1, __shfl_xor_sync(0xffffffffu, tm1, 1));
        tm1 = fmaxf(tm1, __shfl_xor_sync(0xffffffffu, tm1, 2));
        float nm0 = fmaxf(m0r, tm0), nm1 = fmaxf(m1r, tm1);
        float cor0 = __expf(m0r - nm0), cor1 = __expf(m1r - nm1);
        m0r = nm0; m1r = nm1;

        float sum0 = 0.f, sum1 = 0.f;
#pragma unroll
        for (int nt = 0; nt < 8; nt++) {
            s[nt][0] = __expf(s[nt][0] - nm0);
            s[nt][1] = __expf(s[nt][1] - nm0);
            s[nt][2] = __expf(s[nt][2] - nm1);
            s[nt][3] = __expf(s[nt][3] - nm1);
            sum0 += s[nt][0] + s[nt][1];
            sum1 += s[nt][2] + s[nt][3];
        }
        sum0 += __shfl_xor_sync(0xffffffffu, sum0, 1);
        sum0 += __shfl_xor_sync(0xffffffffu, sum0, 2);
        sum1 += __shfl_xor_sync(0xffffffffu, sum1, 1);
        sum1 += __shfl_xor_sync(0xffffffffu, sum1, 2);
        l0 = l0 * cor0 + sum0;
        l1 = l1 * cor1 + sum1;

#pragma unroll
        for (int nt = 0; nt < 16; nt++) {
            o[nt][0] *= cor0; o[nt][1] *= cor0;
            o[nt][2] *= cor1; o[nt][3] *= cor1;
        }

        // ---- O += P @ V : P frags built in-register (fp16) ----
#pragma unroll
        for (int kk = 0; kk < 4; kk++) {
            uint32_t ah[4];
            ah[0] = pack_hf2(s[2 * kk][0],     s[2 * kk][1]);
            ah[1] = pack_hf2(s[2 * kk][2],     s[2 * kk][3]);
            ah[2] = pack_hf2(s[2 * kk + 1][0], s[2 * kk + 1][1]);
            ah[3] = pack_hf2(s[2 * kk + 1][2], s[2 * kk + 1][3]);
#pragma unroll
            for (int nb = 0; nb < 8; nb++) {
                uint32_t v4[4];
                LDM_X4T(v4, vBase + (kk * 16 + l8 * 8 + rin) * AQLD
                            + (nb * 16 + l16 * 8) * 2);
#pragma unroll
                for (int hf = 0; hf < 2; hf++)
                    mma_f16(o[nb * 2 + hf], ah, &v4[hf * 2]);
            }
        }
    }

    // ---- epilogue: normalize + fp16 store for the O-projection ----
    float inv0 = 1.f / l0, inv1 = 1.f / l1;
    const size_t r0 = bbase + q0 + wid * 16 + (lane >> 2);
    const int gc = h * HD + 2 * (lane & 3);
#pragma unroll
    for (int nt = 0; nt < 16; nt++) {
        int col = gc + nt * 8;
        *(uint32_t*)(g_attnb + r0 * HIDD + col) =
            pack_hf2(o[nt][0] * inv0, o[nt][1] * inv0);
        *(uint32_t*)(g_attnb + (r0 + 8) * HIDD + col) =
            pack_hf2(o[nt][2] * inv1, o[nt][3] * inv1);
    }
}

// ---------------------------------------------------------------------------
extern "C" void kernel_launch(void* const* d_in, const int* in_sizes, int n_in,
                              void* d_out, int out_size)
{
    const float* hidden = (const float*)d_in[0];
    const float* fcos   = (const float*)d_in[1];
    const float* fsin   = (const float*)d_in[2];
    const float* w_qkv  = (const float*)d_in[6];
    const float* w_o    = (const float*)d_in[7];
    float* out = (float*)d_out;

    __half *hid, *wqkv, *wo, *qkvb, *attnb;
    cudaGetSymbolAddress((void**)&hid,   g_hid);
    cudaGetSymbolAddress((void**)&wqkv,  g_wqkv);
    cudaGetSymbolAddress((void**)&wo,    g_wo);
    cudaGetSymbolAddress((void**)&qkvb,  g_qkvb);
    cudaGetSymbolAddress((void**)&attnb, g_attnb);

    cudaFuncSetAttribute(gemm_pre_kernel<1>,
                         cudaFuncAttributeMaxDynamicSharedMemorySize, GT_SMEM);
    cudaFuncSetAttribute(gemm_pre_kernel<0>,
                         cudaFuncAttributeMaxDynamicSharedMemorySize, GT_SMEM);
    cudaFuncSetAttribute(attn_kernel,
                         cudaFuncAttributeMaxDynamicSharedMemorySize, ATT_SMEM);

    const int M = BB * TT;  // 4096

    // 0) fused fp32->fp16 conversion (hidden, w_qkv with Q-scale, w_o)
    {
        int total = N4_HID + N4_WQKV + N4_WO;
        convert_all_kernel<<<(total + 255) / 256, 256>>>(hidden, w_qkv, w_o);
    }

    // 1) QKV projection -> g_qkvb fp16 (direct)
    gemm_pre_kernel<1><<<dim3(QKVW / 128, M / 128), 256, GT_SMEM>>>(
        hid, wqkv, qkvb, M, QKVW, HIDD);

    // 2) RoPE in-place on Q,K heads of g_qkvb
    rope16_kernel<<<dim3(BB * TT, 3), 256>>>(fcos, fsin);

    // 3) causal GQA attention (tensor cores) -> g_attnb fp16
    attn_kernel<<<dim3(TT / 64, NH, BB), 128, ATT_SMEM>>>();

    // 4) output projection -> d_out fp32
    gemm_pre_kernel<0><<<dim3(HIDD / 128, M / 128), 256, GT_SMEM>>>(
        attnb, wo, out, M, HIDD, HIDD);
}